// round 4
// baseline (speedup 1.0000x reference)
#include <cuda_runtime.h>

#define FULL 0xffffffffu
#define BNEPS 1e-5f

// ---------------- scratch (device globals; allocation is forbidden) ----------------
__device__ float d_gate[2][64][128][8];   // softmax gates (side, b, t, e)
__device__ float d_hpre[2][8192][16];     // expert layer-1 pre-BN hidden
__device__ float d_part[2][256][32];      // per-block BN partial sums [sum(16) | sumsq(16)]
__device__ float d_bn[2][2][16];          // per-side BN scale/shift
__device__ float d_Wp[128][128];          // repacked ae_w1: [i][e*16+hh]
__device__ float d_xw0[8192][48];         // precomputed main-GRU layer0 input projection
__device__ float d_Zlast[64][16];         // main GRU final hidden
__device__ float d_q[64][128];            // decoder gated hidden (om[e]*h[hh])

__device__ __forceinline__ float sigm(float x) {
    return __fdividef(1.f, 1.f + __expf(-x));
}
__device__ __forceinline__ float tanhf_(float x) {
    return 1.f - __fdividef(2.f, __expf(2.f * x) + 1.f);
}
__device__ __forceinline__ float dot8(const float* w, const float* h) {
    float a0 = fmaf(w[1], h[1], w[0] * h[0]);
    float a1 = fmaf(w[3], h[3], w[2] * h[2]);
    float a2 = fmaf(w[5], h[5], w[4] * h[4]);
    float a3 = fmaf(w[7], h[7], w[6] * h[6]);
    return (a0 + a1) + (a2 + a3);
}
__device__ __forceinline__ float dot16(const float* w, const float* h) {
    float a0 = fmaf(w[1], h[1], w[0] * h[0]);
    a0 = fmaf(w[2], h[2], a0); a0 = fmaf(w[3], h[3], a0);
    float a1 = fmaf(w[5], h[5], w[4] * h[4]);
    a1 = fmaf(w[6], h[6], a1); a1 = fmaf(w[7], h[7], a1);
    float a2 = fmaf(w[9], h[9], w[8] * h[8]);
    a2 = fmaf(w[10], h[10], a2); a2 = fmaf(w[11], h[11], a2);
    float a3 = fmaf(w[13], h[13], w[12] * h[12]);
    a3 = fmaf(w[14], h[14], a3); a3 = fmaf(w[15], h[15], a3);
    return (a0 + a1) + (a2 + a3);
}

// ---------------- K1: repack ae_w1 (8,128,16) -> Wp[i][e*16+hh] ----------------
__global__ void pack_kernel(const float* __restrict__ w1) {
    int idx = blockIdx.x * 256 + threadIdx.x;     // 16384
    int i = idx >> 7, o = idx & 127;
    int e = o >> 4, hh = o & 15;
    d_Wp[i][o] = w1[(e * 128 + i) * 16 + hh];
}

// ---------------- K2: gate GRU (2 layers, hid 8, 128 steps) + softmax ----------------
// one warp per (side, sample); lanes 0-23 own gate rows (r:0-7, z:8-15, n:16-23)
__global__ void __launch_bounds__(128) gate_kernel(
    const float* __restrict__ Local, const float* __restrict__ Remote,
    const float* __restrict__ Wih0, const float* __restrict__ Whh0,
    const float* __restrict__ bih0, const float* __restrict__ bhh0,
    const float* __restrict__ Wih1, const float* __restrict__ Whh1,
    const float* __restrict__ bih1, const float* __restrict__ bhh1)
{
    int warp = blockIdx.x * 4 + (threadIdx.x >> 5);   // 0..127
    int lane = threadIdx.x & 31;
    int side = warp >> 6, b = warp & 63;
    const float* src = side ? Remote : Local;
    int g = (lane < 24) ? lane : 0;
    int j = lane & 7;

    float wi00 = Wih0[g * 3 + 0], wi01 = Wih0[g * 3 + 1], wi02 = Wih0[g * 3 + 2];
    float wh0[8], wi1[8], wh1[8];
#pragma unroll
    for (int k = 0; k < 8; k++) {
        wh0[k] = Whh0[g * 8 + k];
        wi1[k] = Wih1[g * 8 + k];
        wh1[k] = Whh1[g * 8 + k];
    }
    float bi0 = bih0[g], bh0 = bhh0[g], bi1 = bih1[g], bh1 = bhh1[g];

    float h0[8], h1[8];
#pragma unroll
    for (int k = 0; k < 8; k++) { h0[k] = 0.f; h1[k] = 0.f; }
    float own0 = 0.f, own1 = 0.f;

    const float* xb = src + (size_t)b * 16896 + 128;
    float4 xc = *(const float4*)xb;
    float* outp = &d_gate[side][b][0][0];

    for (int t = 0; t < 128; t++) {
        float4 xn = xc;
        if (t < 127) xn = *(const float4*)(xb + (size_t)(t + 1) * 132);
        // layer 0
        float xw = fmaf(xc.z, wi02, fmaf(xc.y, wi01, fmaf(xc.x, wi00, bi0)));
        float gh = dot8(wh0, h0) + bh0;
        float s  = sigm(xw + gh);
        float rr = __shfl_sync(FULL, s, j);
        float nv = tanhf_(fmaf(rr, gh, xw));
        float zz = __shfl_sync(FULL, s, 8 + j);
        float nj = __shfl_sync(FULL, nv, 16 + j);
        float hn0 = fmaf(zz, own0 - nj, nj);
        float no0 = own0;
#pragma unroll
        for (int k = 0; k < 8; k++) {
            float v = __shfl_sync(FULL, hn0, k);
            h0[k] = v;
            if (k == j) no0 = v;
        }
        own0 = no0;
        // layer 1
        float xw1 = dot8(wi1, h0) + bi1;
        float gh1 = dot8(wh1, h1) + bh1;
        float s1  = sigm(xw1 + gh1);
        float rr1 = __shfl_sync(FULL, s1, j);
        float nv1 = tanhf_(fmaf(rr1, gh1, xw1));
        float zz1 = __shfl_sync(FULL, s1, 8 + j);
        float nj1 = __shfl_sync(FULL, nv1, 16 + j);
        float hn1 = fmaf(zz1, own1 - nj1, nj1);
        float no1 = own1;
#pragma unroll
        for (int k = 0; k < 8; k++) {
            float v = __shfl_sync(FULL, hn1, k);
            h1[k] = v;
            if (k == j) no1 = v;
        }
        own1 = no1;
        // softmax over h1 (8)
        float mx = h1[0];
#pragma unroll
        for (int k = 1; k < 8; k++) mx = fmaxf(mx, h1[k]);
        float ev = __expf(own1 - mx);
        float ss = ev;
        ss += __shfl_xor_sync(FULL, ss, 1);
        ss += __shfl_xor_sync(FULL, ss, 2);
        ss += __shfl_xor_sync(FULL, ss, 4);
        if (lane < 8) outp[t * 8 + lane] = __fdividef(ev, ss);
        xc = xn;
    }
}

// ---------------- K3: expert layer-1 GEMM + gate combine + BN partials ----------------
// block: 8 warps x 4 samples; lane owns output quad o = 4*lane (e = lane>>2)
__global__ void __launch_bounds__(256) expert1_kernel(
    const float* __restrict__ Local, const float* __restrict__ Remote,
    const float* __restrict__ b1)
{
    int side = blockIdx.y;
    const float* src = side ? Remote : Local;
    int w = threadIdx.x >> 5, lane = threadIdx.x & 31;
    int n0 = blockIdx.x * 32 + w * 4;

    __shared__ __align__(16) float xs[8][4][128];
    __shared__ float swp[8][32];

#pragma unroll
    for (int s = 0; s < 4; s++) {
        int n = n0 + s;
        int b = n >> 7, t = n & 127;
        float4 v = *(const float4*)(src + (size_t)b * 16896 + t * 132 + lane * 4);
        *(float4*)&xs[w][s][lane * 4] = v;
    }
    int e = lane >> 2;
    const float* gp = &d_gate[0][0][0][0];
    size_t gbase = (size_t)side * 8192 + n0;
    float g0 = gp[(gbase + 0) * 8 + e];
    float g1 = gp[(gbase + 1) * 8 + e];
    float g2 = gp[(gbase + 2) * 8 + e];
    float g3 = gp[(gbase + 3) * 8 + e];
    __syncthreads();

    float4 a0 = {0, 0, 0, 0}, a1 = {0, 0, 0, 0}, a2 = {0, 0, 0, 0}, a3 = {0, 0, 0, 0};
    const float4* Wp4 = (const float4*)d_Wp;
#pragma unroll 4
    for (int i = 0; i < 128; i++) {
        float4 wv = Wp4[i * 32 + lane];
        float x0 = xs[w][0][i], x1 = xs[w][1][i], x2 = xs[w][2][i], x3 = xs[w][3][i];
        a0.x = fmaf(x0, wv.x, a0.x); a0.y = fmaf(x0, wv.y, a0.y);
        a0.z = fmaf(x0, wv.z, a0.z); a0.w = fmaf(x0, wv.w, a0.w);
        a1.x = fmaf(x1, wv.x, a1.x); a1.y = fmaf(x1, wv.y, a1.y);
        a1.z = fmaf(x1, wv.z, a1.z); a1.w = fmaf(x1, wv.w, a1.w);
        a2.x = fmaf(x2, wv.x, a2.x); a2.y = fmaf(x2, wv.y, a2.y);
        a2.z = fmaf(x2, wv.z, a2.z); a2.w = fmaf(x2, wv.w, a2.w);
        a3.x = fmaf(x3, wv.x, a3.x); a3.y = fmaf(x3, wv.y, a3.y);
        a3.z = fmaf(x3, wv.z, a3.z); a3.w = fmaf(x3, wv.w, a3.w);
    }
    float4 bq = ((const float4*)b1)[lane];
    a0.x = (a0.x + bq.x) * g0; a0.y = (a0.y + bq.y) * g0; a0.z = (a0.z + bq.z) * g0; a0.w = (a0.w + bq.w) * g0;
    a1.x = (a1.x + bq.x) * g1; a1.y = (a1.y + bq.y) * g1; a1.z = (a1.z + bq.z) * g1; a1.w = (a1.w + bq.w) * g1;
    a2.x = (a2.x + bq.x) * g2; a2.y = (a2.y + bq.y) * g2; a2.z = (a2.z + bq.z) * g2; a2.w = (a2.w + bq.w) * g2;
    a3.x = (a3.x + bq.x) * g3; a3.y = (a3.y + bq.y) * g3; a3.z = (a3.z + bq.z) * g3; a3.w = (a3.w + bq.w) * g3;
#pragma unroll
    for (int o = 4; o < 32; o <<= 1) {
        a0.x += __shfl_xor_sync(FULL, a0.x, o); a0.y += __shfl_xor_sync(FULL, a0.y, o);
        a0.z += __shfl_xor_sync(FULL, a0.z, o); a0.w += __shfl_xor_sync(FULL, a0.w, o);
        a1.x += __shfl_xor_sync(FULL, a1.x, o); a1.y += __shfl_xor_sync(FULL, a1.y, o);
        a1.z += __shfl_xor_sync(FULL, a1.z, o); a1.w += __shfl_xor_sync(FULL, a1.w, o);
        a2.x += __shfl_xor_sync(FULL, a2.x, o); a2.y += __shfl_xor_sync(FULL, a2.y, o);
        a2.z += __shfl_xor_sync(FULL, a2.z, o); a2.w += __shfl_xor_sync(FULL, a2.w, o);
        a3.x += __shfl_xor_sync(FULL, a3.x, o); a3.y += __shfl_xor_sync(FULL, a3.y, o);
        a3.z += __shfl_xor_sync(FULL, a3.z, o); a3.w += __shfl_xor_sync(FULL, a3.w, o);
    }
    if (lane < 4) {
        float4 vs0 = a0, vs1 = a1, vs2 = a2, vs3 = a3;
        *(float4*)&d_hpre[side][n0 + 0][lane * 4] = vs0;
        *(float4*)&d_hpre[side][n0 + 1][lane * 4] = vs1;
        *(float4*)&d_hpre[side][n0 + 2][lane * 4] = vs2;
        *(float4*)&d_hpre[side][n0 + 3][lane * 4] = vs3;
        float sx0 = vs0.x + vs1.x + vs2.x + vs3.x;
        float sx1 = vs0.y + vs1.y + vs2.y + vs3.y;
        float sx2 = vs0.z + vs1.z + vs2.z + vs3.z;
        float sx3 = vs0.w + vs1.w + vs2.w + vs3.w;
        float q0 = vs0.x * vs0.x + vs1.x * vs1.x + vs2.x * vs2.x + vs3.x * vs3.x;
        float q1 = vs0.y * vs0.y + vs1.y * vs1.y + vs2.y * vs2.y + vs3.y * vs3.y;
        float q2 = vs0.z * vs0.z + vs1.z * vs1.z + vs2.z * vs2.z + vs3.z * vs3.z;
        float q3 = vs0.w * vs0.w + vs1.w * vs1.w + vs2.w * vs2.w + vs3.w * vs3.w;
        int c = lane * 4;
        swp[w][c + 0] = sx0; swp[w][c + 1] = sx1; swp[w][c + 2] = sx2; swp[w][c + 3] = sx3;
        swp[w][16 + c + 0] = q0; swp[w][16 + c + 1] = q1; swp[w][16 + c + 2] = q2; swp[w][16 + c + 3] = q3;
    }
    __syncthreads();
    if (threadIdx.x < 32) {
        float acc = 0.f;
#pragma unroll
        for (int ww = 0; ww < 8; ww++) acc += swp[ww][threadIdx.x];
        d_part[side][blockIdx.x][threadIdx.x] = acc;
    }
}

// ---------------- K4: BN finalize ----------------
__global__ void bnfin_kernel(const float* __restrict__ ae_g, const float* __restrict__ ae_bt) {
    int t = threadIdx.x;       // 32
    int side = t >> 4, ch = t & 15;
    float s = 0.f, s2 = 0.f;
#pragma unroll 8
    for (int bk = 0; bk < 256; bk++) {
        s += d_part[side][bk][ch];
        s2 += d_part[side][bk][16 + ch];
    }
    float m = s * (1.f / 8192.f);
    float v = s2 * (1.f / 8192.f) - m * m;
    float a = ae_g[ch] * rsqrtf(v + BNEPS);
    d_bn[side][0][ch] = a;
    d_bn[side][1][ch] = ae_bt[ch] - m * a;
}

// ---------------- K5: BN+ELU + expert layer-2 + main-GRU input projection ----------------
__global__ void __launch_bounds__(128) zxw_kernel(
    const float* __restrict__ w2, const float* __restrict__ b2,
    const float* __restrict__ mWih0, const float* __restrict__ mbih0)
{
    int n = blockIdx.x * 128 + threadIdx.x;   // 8192
    const float* gp = &d_gate[0][0][0][0];
    float Z[16];
#pragma unroll
    for (int k = 0; k < 16; k++) Z[k] = 0.f;
#pragma unroll
    for (int side = 0; side < 2; side++) {
        float h[16];
#pragma unroll
        for (int k = 0; k < 16; k++) {
            float a = d_bn[side][0][k] * d_hpre[side][n][k] + d_bn[side][1][k];
            h[k] = a > 0.f ? a : (__expf(a) - 1.f);
        }
        float om[8];
#pragma unroll
        for (int ee = 0; ee < 8; ee++) om[ee] = gp[((size_t)side * 8192 + n) * 8 + ee];
#pragma unroll 1
        for (int ee = 0; ee < 8; ee++) {
            float c = om[ee];
#pragma unroll
            for (int o = 0; o < 16; o++) {
                float acc = b2[ee * 16 + o];
#pragma unroll
                for (int hh = 0; hh < 16; hh++)
                    acc = fmaf(h[hh], w2[ee * 256 + hh * 16 + o], acc);
                Z[o] = fmaf(c, acc, Z[o]);
            }
        }
    }
#pragma unroll 1
    for (int g48 = 0; g48 < 48; g48++) {
        float acc = mbih0[g48];
#pragma unroll
        for (int hh = 0; hh < 16; hh++) acc = fmaf(Z[hh], mWih0[g48 * 16 + hh], acc);
        d_xw0[n][g48] = acc;
    }
}

// ---------------- K6: main GRU (2 layers, hid 16) ----------------
// warp per sample; lanes 0-15 own r&n rows for j=lane, lanes 16-31 own z row j=lane-16
__global__ void __launch_bounds__(32) mgru_kernel(
    const float* __restrict__ Whh0, const float* __restrict__ bhh0_,
    const float* __restrict__ Wih1, const float* __restrict__ bih1_,
    const float* __restrict__ Whh1, const float* __restrict__ bhh1_)
{
    int b = blockIdx.x;
    int lane = threadIdx.x;
    int j = lane & 15;
    int rowA = (lane < 16) ? lane : 16 + j;
    int rowB = 32 + j;
    float whA[16], whB[16], wiA1[16], wiB1[16], whA1[16], whB1[16];
#pragma unroll
    for (int k = 0; k < 16; k++) {
        whA[k] = Whh0[rowA * 16 + k];  whB[k] = Whh0[rowB * 16 + k];
        wiA1[k] = Wih1[rowA * 16 + k]; wiB1[k] = Wih1[rowB * 16 + k];
        whA1[k] = Whh1[rowA * 16 + k]; whB1[k] = Whh1[rowB * 16 + k];
    }
    float bhA = bhh0_[rowA], bhB = bhh0_[rowB];
    float biA1 = bih1_[rowA], biB1 = bih1_[rowB];
    float bhA1 = bhh1_[rowA], bhB1 = bhh1_[rowB];
    float h0[16], h1[16];
#pragma unroll
    for (int k = 0; k < 16; k++) { h0[k] = 0.f; h1[k] = 0.f; }
    float own0 = 0.f, own1 = 0.f;
    const float* xwp = &d_xw0[b * 128][0];
    float xwA = xwp[rowA], xwB = xwp[rowB];
    for (int t = 0; t < 128; t++) {
        float nxA = 0.f, nxB = 0.f;
        if (t < 127) { nxA = xwp[(t + 1) * 48 + rowA]; nxB = xwp[(t + 1) * 48 + rowB]; }
        // layer 0
        float ghA = dot16(whA, h0) + bhA;
        float s = sigm(xwA + ghA);                  // lanes<16: r, lanes>=16: z
        float ghB = dot16(whB, h0) + bhB;
        float n = tanhf_(fmaf(s, ghB, xwB));        // valid on lanes<16
        float z = __shfl_sync(FULL, s, 16 + j);
        float nn = __shfl_sync(FULL, n, j);
        float hn = fmaf(z, own0 - nn, nn);
        float no0 = own0;
#pragma unroll
        for (int k = 0; k < 16; k++) {
            float v = __shfl_sync(FULL, hn, k);
            h0[k] = v;
            if (k == j) no0 = v;
        }
        own0 = no0;
        // layer 1
        float xwA1 = dot16(wiA1, h0) + biA1;
        float ghA1 = dot16(whA1, h1) + bhA1;
        float s1 = sigm(xwA1 + ghA1);
        float xwB1 = dot16(wiB1, h0) + biB1;
        float ghB1 = dot16(whB1, h1) + bhB1;
        float n1 = tanhf_(fmaf(s1, ghB1, xwB1));
        float z1 = __shfl_sync(FULL, s1, 16 + j);
        float nn1 = __shfl_sync(FULL, n1, j);
        float hn1 = fmaf(z1, own1 - nn1, nn1);
        float no1 = own1;
#pragma unroll
        for (int k = 0; k < 16; k++) {
            float v = __shfl_sync(FULL, hn1, k);
            h1[k] = v;
            if (k == j) no1 = v;
        }
        own1 = no1;
        xwA = nxA; xwB = nxB;
    }
    if (lane < 16) d_Zlast[b][lane] = h1[lane];
}

// ---------------- K7: decoder expert layer-1 + BN + ELU + gate-weighting ----------------
__global__ void __launch_bounds__(64) dec1_kernel(
    const float* __restrict__ Remote,
    const float* __restrict__ w1, const float* __restrict__ b1,
    const float* __restrict__ gmd, const float* __restrict__ btmd)
{
    int b = threadIdx.x;     // 64
    __shared__ float sh[64][16];
    __shared__ float sa[16], sc[16];
    float x[17];
#pragma unroll
    for (int k = 0; k < 16; k++) x[k] = d_Zlast[b][k];
    x[16] = Remote[(size_t)b * 16896 + 127 * 132 + 131];
    const float* gp = &d_gate[0][0][0][0];
    float om[8];
#pragma unroll
    for (int e = 0; e < 8; e++) om[e] = gp[(size_t)(8192 + b * 128 + 127) * 8 + e];
    float h[16];
#pragma unroll
    for (int hh = 0; hh < 16; hh++) {
        float acc = 0.f;
#pragma unroll 1
        for (int e = 0; e < 8; e++) {
            float a = b1[e * 16 + hh];
#pragma unroll
            for (int i = 0; i < 17; i++) a = fmaf(x[i], w1[e * 272 + i * 16 + hh], a);
            acc = fmaf(om[e], a, acc);
        }
        h[hh] = acc;
        sh[b][hh] = acc;
    }
    __syncthreads();
    if (b < 16) {
        float s = 0.f, s2 = 0.f;
#pragma unroll 8
        for (int bb = 0; bb < 64; bb++) {
            float v = sh[bb][b];
            s += v; s2 += v * v;
        }
        float m = s * (1.f / 64.f);
        float vv = s2 * (1.f / 64.f) - m * m;
        float a = gmd[b] * rsqrtf(vv + BNEPS);
        sa[b] = a;
        sc[b] = btmd[b] - m * a;
    }
    __syncthreads();
#pragma unroll
    for (int hh = 0; hh < 16; hh++) {
        float t = sa[hh] * h[hh] + sc[hh];
        h[hh] = t > 0.f ? t : (__expf(t) - 1.f);
    }
#pragma unroll 1
    for (int e = 0; e < 8; e++) {
        float c = om[e];
#pragma unroll
        for (int hh = 0; hh < 16; hh++) d_q[b][e * 16 + hh] = c * h[hh];
    }
}

// ---------------- K8: decoder layer-2 -> output ----------------
__global__ void __launch_bounds__(128) dec2_kernel(
    const float* __restrict__ w2, const float* __restrict__ b2,
    float* __restrict__ out)
{
    int b = blockIdx.x, o = threadIdx.x;
    __shared__ float sq[128];
    sq[o] = d_q[b][o];
    __syncthreads();
    const float* gp = &d_gate[0][0][0][0];
    float acc = 0.f;
#pragma unroll 4
    for (int k = 0; k < 128; k++) acc = fmaf(sq[k], w2[k * 128 + o], acc);
#pragma unroll
    for (int e = 0; e < 8; e++)
        acc = fmaf(gp[(size_t)(8192 + b * 128 + 127) * 8 + e], b2[e * 128 + o], acc);
    out[b * 128 + o] = acc;
}

// ---------------- host ----------------
extern "C" void kernel_launch(void* const* d_in, const int* in_sizes, int n_in,
                              void* d_out, int out_size) {
    const float* Local = (const float*)d_in[0];
    const float* Remote = (const float*)d_in[1];
    const float *gWih0, *gWhh0, *gbih0, *gbhh0, *gWih1, *gWhh1, *gbih1, *gbhh1;
    const float *aew1, *aeb1, *aew2, *aeb2, *aeg, *aebt;
    const float *mdw1, *mdb1, *mdw2, *mdb2, *mdg, *mdbt;
    const float *mWih0, *mWhh0, *mbih0, *mbhh0, *mWih1, *mWhh1, *mbih1, *mbhh1;
#define FP(i) ((const float*)d_in[(i)])
    if (in_sizes[2] == 72) {
        gWih0 = FP(2); gWhh0 = FP(3); gbih0 = FP(4); gbhh0 = FP(5);
        gWih1 = FP(6); gWhh1 = FP(7); gbih1 = FP(8); gbhh1 = FP(9);
        int ae, m;
        if (in_sizes[10] == 16384) { ae = 10; m = 22; }   // signature order
        else                       { m = 10; ae = 18; }   // setup_inputs dict order
        aew1 = FP(ae + 0); aeb1 = FP(ae + 1); aew2 = FP(ae + 2);
        aeb2 = FP(ae + 3); aeg  = FP(ae + 4); aebt = FP(ae + 5);
        mdw1 = FP(ae + 6); mdb1 = FP(ae + 7); mdw2 = FP(ae + 8);
        mdb2 = FP(ae + 9); mdg  = FP(ae + 10); mdbt = FP(ae + 11);
        mWih0 = FP(m + 0); mWhh0 = FP(m + 1); mbih0 = FP(m + 2); mbhh0 = FP(m + 3);
        mWih1 = FP(m + 4); mWhh1 = FP(m + 5); mbih1 = FP(m + 6); mbhh1 = FP(m + 7);
    } else {
        // alphabetical fallback
        aeb1 = FP(2); aeb2 = FP(3); aebt = FP(4); aeg = FP(5); aew1 = FP(6); aew2 = FP(7);
        gWhh0 = FP(8); gWhh1 = FP(9); gWih0 = FP(10); gWih1 = FP(11);
        gbhh0 = FP(12); gbhh1 = FP(13); gbih0 = FP(14); gbih1 = FP(15);
        mWhh0 = FP(16); mWhh1 = FP(17); mWih0 = FP(18); mWih1 = FP(19);
        mbhh0 = FP(20); mbhh1 = FP(21); mbih0 = FP(22); mbih1 = FP(23);
        mdb1 = FP(24); mdb2 = FP(25); mdbt = FP(26); mdg = FP(27); mdw1 = FP(28); mdw2 = FP(29);
    }
#undef FP
    float* out = (float*)d_out;

    pack_kernel<<<64, 256>>>(aew1);
    gate_kernel<<<32, 128>>>(Local, Remote, gWih0, gWhh0, gbih0, gbhh0,
                             gWih1, gWhh1, gbih1, gbhh1);
    expert1_kernel<<<dim3(256, 2), 256>>>(Local, Remote, aeb1);
    bnfin_kernel<<<1, 32>>>(aeg, aebt);
    zxw_kernel<<<64, 128>>>(aew2, aeb2, mWih0, mbih0);
    mgru_kernel<<<64, 32>>>(mWhh0, mbhh0, mWih1, mbih1, mWhh1, mbhh1);
    dec1_kernel<<<1, 64>>>(Remote, mdw1, mdb1, mdg, mdbt);
    dec2_kernel<<<64, 128>>>(mdw2, mdb2, out);
}

// round 5
// speedup vs baseline: 1.9904x; 1.9904x over previous
#include <cuda_runtime.h>

#define FULL 0xffffffffu
#define BNEPS 1e-5f

// ---------------- scratch (device globals; allocation is forbidden) ----------------
__device__ float d_gate[2][64][128][8];   // softmax gates (side, b, t, e)
__device__ float d_hpre[2][8192][16];     // expert layer-1 pre-BN hidden
__device__ float d_part[2][256][32];      // per-block BN partial sums [sum(16) | sumsq(16)]
__device__ float d_bn[2][2][16];          // per-side BN scale/shift
__device__ float d_xw0[8192][48];         // precomputed main-GRU layer0 input projection
__device__ float d_Zlast[64][16];         // main GRU final hidden
__device__ float d_q[64][128];            // decoder gated hidden (om[e]*h[hh])

// ---------------- fast math ----------------
__device__ __forceinline__ float tanha(float x) {
    float y;
    asm("tanh.approx.f32 %0, %1;" : "=f"(y) : "f"(x));
    return y;
}
__device__ __forceinline__ float sigt(float x) {          // sigmoid via tanh
    return fmaf(tanha(0.5f * x), 0.5f, 0.5f);
}
__device__ __forceinline__ unsigned long long pack2(float x, float y) {
    unsigned long long r;
    asm("mov.b64 %0, {%1, %2};" : "=l"(r) : "f"(x), "f"(y));
    return r;
}
__device__ __forceinline__ void unpack2(unsigned long long v, float& x, float& y) {
    asm("mov.b64 {%0, %1}, %2;" : "=f"(x), "=f"(y) : "l"(v));
}
__device__ __forceinline__ unsigned long long fma2(unsigned long long a,
                                                   unsigned long long b,
                                                   unsigned long long c) {
    unsigned long long d;
    asm("fma.rn.f32x2 %0, %1, %2, %3;" : "=l"(d) : "l"(a), "l"(b), "l"(c));
    return d;
}
__device__ __forceinline__ float dot8(const float* w, const float* h) {
    float a0 = fmaf(w[1], h[1], w[0] * h[0]);
    float a1 = fmaf(w[3], h[3], w[2] * h[2]);
    float a2 = fmaf(w[5], h[5], w[4] * h[4]);
    float a3 = fmaf(w[7], h[7], w[6] * h[6]);
    return (a0 + a1) + (a2 + a3);
}
__device__ __forceinline__ float dot16(const float* w, const float* h) {
    float a0 = fmaf(w[1], h[1], w[0] * h[0]);
    a0 = fmaf(w[2], h[2], a0); a0 = fmaf(w[3], h[3], a0);
    float a1 = fmaf(w[5], h[5], w[4] * h[4]);
    a1 = fmaf(w[6], h[6], a1); a1 = fmaf(w[7], h[7], a1);
    float a2 = fmaf(w[9], h[9], w[8] * h[8]);
    a2 = fmaf(w[10], h[10], a2); a2 = fmaf(w[11], h[11], a2);
    float a3 = fmaf(w[13], h[13], w[12] * h[12]);
    a3 = fmaf(w[14], h[14], a3); a3 = fmaf(w[15], h[15], a3);
    return (a0 + a1) + (a2 + a3);
}

// ---------------- K2: gate GRU, Local+Remote paired in one warp ----------------
// warp per sample b; lanes 0-23 own gate rows (r:0-7, z:8-15, n:16-23)
__global__ void __launch_bounds__(128) gate_kernel(
    const float* __restrict__ Local, const float* __restrict__ Remote,
    const float* __restrict__ Wih0, const float* __restrict__ Whh0,
    const float* __restrict__ bih0, const float* __restrict__ bhh0,
    const float* __restrict__ Wih1, const float* __restrict__ Whh1,
    const float* __restrict__ bih1, const float* __restrict__ bhh1)
{
    int b = blockIdx.x * 4 + (threadIdx.x >> 5);      // 0..63
    int lane = threadIdx.x & 31;
    int g = (lane < 24) ? lane : 0;
    int j = lane & 7;

    float wi00 = Wih0[g * 3 + 0], wi01 = Wih0[g * 3 + 1], wi02 = Wih0[g * 3 + 2];
    float wh0[8], wi1[8], wh1[8];
#pragma unroll
    for (int k = 0; k < 8; k++) {
        wh0[k] = Whh0[g * 8 + k];
        wi1[k] = Wih1[g * 8 + k];
        wh1[k] = Whh1[g * 8 + k];
    }
    float bi0 = bih0[g], bh0 = bhh0[g], bi1 = bih1[g], bh1 = bhh1[g];

    float hL0[8], hL1[8], hR0[8], hR1[8];
#pragma unroll
    for (int k = 0; k < 8; k++) { hL0[k] = 0.f; hL1[k] = 0.f; hR0[k] = 0.f; hR1[k] = 0.f; }
    float oL0 = 0.f, oL1 = 0.f, oR0 = 0.f, oR1 = 0.f;

    const float* xbL = Local + (size_t)b * 16896 + 128;
    const float* xbR = Remote + (size_t)b * 16896 + 128;
    float4 xL = *(const float4*)xbL;
    float4 xR = *(const float4*)xbR;
    float* outL = &d_gate[0][b][0][0];
    float* outR = &d_gate[1][b][0][0];

    for (int t = 0; t < 128; t++) {
        float4 nLx = xL, nRx = xR;
        if (t < 127) {
            nLx = *(const float4*)(xbL + (size_t)(t + 1) * 132);
            nRx = *(const float4*)(xbR + (size_t)(t + 1) * 132);
        }
        // ---- layer 0 (both sides interleaved for ILP) ----
        float xwL = fmaf(xL.z, wi02, fmaf(xL.y, wi01, fmaf(xL.x, wi00, bi0)));
        float xwR = fmaf(xR.z, wi02, fmaf(xR.y, wi01, fmaf(xR.x, wi00, bi0)));
        float ghL = dot8(wh0, hL0) + bh0;
        float ghR = dot8(wh0, hR0) + bh0;
        float sL = sigt(xwL + ghL);
        float sR = sigt(xwR + ghR);
        float rL = __shfl_sync(FULL, sL, j);
        float rR = __shfl_sync(FULL, sR, j);
        float zL = __shfl_sync(FULL, sL, 8 + j);
        float zR = __shfl_sync(FULL, sR, 8 + j);
        float nvL = tanha(fmaf(rL, ghL, xwL));
        float nvR = tanha(fmaf(rR, ghR, xwR));
        float hnL = fmaf(zL, oL0 - nvL, nvL);     // valid on n-lanes 16-23
        float hnR = fmaf(zR, oR0 - nvR, nvR);
        {
            float t0 = oL0, t1 = oR0;
#pragma unroll
            for (int k = 0; k < 8; k++) {
                float vL = __shfl_sync(FULL, hnL, 16 + k);
                float vR = __shfl_sync(FULL, hnR, 16 + k);
                hL0[k] = vL; hR0[k] = vR;
                if (k == j) { t0 = vL; t1 = vR; }
            }
            oL0 = t0; oR0 = t1;
        }
        // ---- layer 1 ----
        float xw1L = dot8(wi1, hL0) + bi1;
        float xw1R = dot8(wi1, hR0) + bi1;
        float gh1L = dot8(wh1, hL1) + bh1;
        float gh1R = dot8(wh1, hR1) + bh1;
        float s1L = sigt(xw1L + gh1L);
        float s1R = sigt(xw1R + gh1R);
        float r1L = __shfl_sync(FULL, s1L, j);
        float r1R = __shfl_sync(FULL, s1R, j);
        float z1L = __shfl_sync(FULL, s1L, 8 + j);
        float z1R = __shfl_sync(FULL, s1R, 8 + j);
        float nv1L = tanha(fmaf(r1L, gh1L, xw1L));
        float nv1R = tanha(fmaf(r1R, gh1R, xw1R));
        float hn1L = fmaf(z1L, oL1 - nv1L, nv1L);
        float hn1R = fmaf(z1R, oR1 - nv1R, nv1R);
        {
            float t0 = oL1, t1 = oR1;
#pragma unroll
            for (int k = 0; k < 8; k++) {
                float vL = __shfl_sync(FULL, hn1L, 16 + k);
                float vR = __shfl_sync(FULL, hn1R, 16 + k);
                hL1[k] = vL; hR1[k] = vR;
                if (k == j) { t0 = vL; t1 = vR; }
            }
            oL1 = t0; oR1 = t1;
        }
        // ---- softmax (h1 in (-1,1): no max shift needed; off critical path) ----
        float evL = __expf(oL1);
        float evR = __expf(oR1);
        float ssL = evL, ssR = evR;
        ssL += __shfl_xor_sync(FULL, ssL, 1); ssR += __shfl_xor_sync(FULL, ssR, 1);
        ssL += __shfl_xor_sync(FULL, ssL, 2); ssR += __shfl_xor_sync(FULL, ssR, 2);
        ssL += __shfl_xor_sync(FULL, ssL, 4); ssR += __shfl_xor_sync(FULL, ssR, 4);
        if (lane < 8) {
            outL[t * 8 + lane] = __fdividef(evL, ssL);
            outR[t * 8 + lane] = __fdividef(evR, ssR);
        }
        xL = nLx; xR = nRx;
    }
}

// ---------------- K3: expert layer-1 GEMM (f32x2) + gate combine + BN partials ----------------
// block: 4 warps x 8 samples; lane owns outputs o = 4*lane..4*lane+3 (e = lane>>2, hh = 4*(lane&3))
__global__ void __launch_bounds__(128) expert1_kernel(
    const float* __restrict__ Local, const float* __restrict__ Remote,
    const float* __restrict__ w1, const float* __restrict__ b1)
{
    int side = blockIdx.y;
    const float* src = side ? Remote : Local;
    int w = threadIdx.x >> 5, lane = threadIdx.x & 31;
    int n0 = blockIdx.x * 32 + w * 8;

    __shared__ __align__(16) float2 xs2[4][8][128];   // duplicated x for LDS.64 -> (x,x)
    __shared__ float swp[4][32];

#pragma unroll
    for (int s = 0; s < 8; s++) {
        int n = n0 + s;
        int bb = n >> 7, t = n & 127;
        float4 v = *(const float4*)(src + (size_t)bb * 16896 + t * 132 + lane * 4);
        xs2[w][s][lane * 4 + 0] = make_float2(v.x, v.x);
        xs2[w][s][lane * 4 + 1] = make_float2(v.y, v.y);
        xs2[w][s][lane * 4 + 2] = make_float2(v.z, v.z);
        xs2[w][s][lane * 4 + 3] = make_float2(v.w, v.w);
    }
    int e = lane >> 2, hq = lane & 3;
    const float* gp = &d_gate[0][0][0][0];
    float gg[8];
#pragma unroll
    for (int s = 0; s < 8; s++) gg[s] = gp[((size_t)side * 8192 + n0 + s) * 8 + e];
    __syncthreads();

    unsigned long long a01[8], a23[8];
#pragma unroll
    for (int s = 0; s < 8; s++) { a01[s] = 0ull; a23[s] = 0ull; }

    const float* wbase = w1 + (size_t)e * 2048 + hq * 4;   // (e*128+i)*16 + 4*hq
#pragma unroll 4
    for (int i = 0; i < 128; i++) {
        float4 wv = *(const float4*)(wbase + i * 16);
        unsigned long long w01 = pack2(wv.x, wv.y);
        unsigned long long w23 = pack2(wv.z, wv.w);
#pragma unroll
        for (int s = 0; s < 8; s++) {
            unsigned long long xp = *(const unsigned long long*)&xs2[w][s][i];
            a01[s] = fma2(w01, xp, a01[s]);
            a23[s] = fma2(w23, xp, a23[s]);
        }
    }
    float4 bq = *(const float4*)(b1 + e * 16 + hq * 4);
    float vv[8][4];
#pragma unroll
    for (int s = 0; s < 8; s++) {
        float v0, v1, v2, v3;
        unpack2(a01[s], v0, v1);
        unpack2(a23[s], v2, v3);
        v0 = (v0 + bq.x) * gg[s]; v1 = (v1 + bq.y) * gg[s];
        v2 = (v2 + bq.z) * gg[s]; v3 = (v3 + bq.w) * gg[s];
#pragma unroll
        for (int o = 4; o < 32; o <<= 1) {
            v0 += __shfl_xor_sync(FULL, v0, o);
            v1 += __shfl_xor_sync(FULL, v1, o);
            v2 += __shfl_xor_sync(FULL, v2, o);
            v3 += __shfl_xor_sync(FULL, v3, o);
        }
        vv[s][0] = v0; vv[s][1] = v1; vv[s][2] = v2; vv[s][3] = v3;
    }
    if (lane < 4) {                           // lane = hq group, hh quad = 4*lane
        float sx[4] = {0, 0, 0, 0}, sq[4] = {0, 0, 0, 0};
#pragma unroll
        for (int s = 0; s < 8; s++) {
            *(float4*)&d_hpre[side][n0 + s][lane * 4] =
                make_float4(vv[s][0], vv[s][1], vv[s][2], vv[s][3]);
#pragma unroll
            for (int c = 0; c < 4; c++) {
                sx[c] += vv[s][c];
                sq[c] = fmaf(vv[s][c], vv[s][c], sq[c]);
            }
        }
#pragma unroll
        for (int c = 0; c < 4; c++) {
            swp[w][lane * 4 + c] = sx[c];
            swp[w][16 + lane * 4 + c] = sq[c];
        }
    }
    __syncthreads();
    if (threadIdx.x < 32) {
        float acc = swp[0][threadIdx.x] + swp[1][threadIdx.x] +
                    swp[2][threadIdx.x] + swp[3][threadIdx.x];
        d_part[side][blockIdx.x][threadIdx.x] = acc;
    }
}

// ---------------- K4: BN finalize (parallel reduction) ----------------
__global__ void __launch_bounds__(1024) bnfin_kernel(
    const float* __restrict__ ae_g, const float* __restrict__ ae_bt)
{
    __shared__ float sp[2][32][16];
    int t = threadIdx.x;                     // 1024
    int side = t >> 9, rem = t & 511;
    int ch = rem & 31, chunk = rem >> 5;     // chunk 0..15
    float s = 0.f;
#pragma unroll
    for (int k = 0; k < 16; k++) s += d_part[side][chunk * 16 + k][ch];
    sp[side][ch][chunk] = s;
    __syncthreads();
    if (t < 32) {
        int sd = t >> 4, c = t & 15;
        float su = 0.f, sq = 0.f;
#pragma unroll
        for (int k = 0; k < 16; k++) {
            su += sp[sd][c][k];
            sq += sp[sd][16 + c][k];
        }
        float m = su * (1.f / 8192.f);
        float v = sq * (1.f / 8192.f) - m * m;
        float a = ae_g[c] * rsqrtf(v + BNEPS);
        d_bn[sd][0][c] = a;
        d_bn[sd][1][c] = ae_bt[c] - m * a;
    }
}

// ---------------- K5: BN+ELU + expert layer-2 + main-GRU input projection ----------------
__global__ void __launch_bounds__(128) zxw_kernel(
    const float* __restrict__ w2, const float* __restrict__ b2,
    const float* __restrict__ mWih0, const float* __restrict__ mbih0)
{
    int n = blockIdx.x * 128 + threadIdx.x;   // 8192
    const float* gp = &d_gate[0][0][0][0];
    float Z[16];
#pragma unroll
    for (int k = 0; k < 16; k++) Z[k] = 0.f;
#pragma unroll
    for (int side = 0; side < 2; side++) {
        float h[16];
#pragma unroll
        for (int k = 0; k < 16; k++) {
            float a = d_bn[side][0][k] * d_hpre[side][n][k] + d_bn[side][1][k];
            h[k] = a > 0.f ? a : (__expf(a) - 1.f);
        }
        float om[8];
#pragma unroll
        for (int ee = 0; ee < 8; ee++) om[ee] = gp[((size_t)side * 8192 + n) * 8 + ee];
#pragma unroll 1
        for (int ee = 0; ee < 8; ee++) {
            float c = om[ee];
#pragma unroll
            for (int o = 0; o < 16; o++) {
                float acc = b2[ee * 16 + o];
#pragma unroll
                for (int hh = 0; hh < 16; hh++)
                    acc = fmaf(h[hh], w2[ee * 256 + hh * 16 + o], acc);
                Z[o] = fmaf(c, acc, Z[o]);
            }
        }
    }
#pragma unroll 1
    for (int g48 = 0; g48 < 48; g48++) {
        float acc = mbih0[g48];
#pragma unroll
        for (int hh = 0; hh < 16; hh++) acc = fmaf(Z[hh], mWih0[g48 * 16 + hh], acc);
        d_xw0[n][g48] = acc;
    }
}

// ---------------- K6: main GRU (2 layers, hid 16) ----------------
// warp per sample; lanes 0-15 own r&n rows for j=lane, lanes 16-31 own z row
__global__ void __launch_bounds__(32) mgru_kernel(
    const float* __restrict__ Whh0, const float* __restrict__ bhh0_,
    const float* __restrict__ Wih1, const float* __restrict__ bih1_,
    const float* __restrict__ Whh1, const float* __restrict__ bhh1_)
{
    int b = blockIdx.x;
    int lane = threadIdx.x;
    int j = lane & 15;
    int rowA = (lane < 16) ? lane : 16 + j;
    int rowB = 32 + j;
    float whA[16], whB[16], wiA1[16], wiB1[16], whA1[16], whB1[16];
#pragma unroll
    for (int k = 0; k < 16; k++) {
        whA[k] = Whh0[rowA * 16 + k];  whB[k] = Whh0[rowB * 16 + k];
        wiA1[k] = Wih1[rowA * 16 + k]; wiB1[k] = Wih1[rowB * 16 + k];
        whA1[k] = Whh1[rowA * 16 + k]; whB1[k] = Whh1[rowB * 16 + k];
    }
    float bhA = bhh0_[rowA], bhB = bhh0_[rowB];
    float biA1 = bih1_[rowA], biB1 = bih1_[rowB];
    float bhA1 = bhh1_[rowA], bhB1 = bhh1_[rowB];
    float h0[16], h1[16];
#pragma unroll
    for (int k = 0; k < 16; k++) { h0[k] = 0.f; h1[k] = 0.f; }
    float own0 = 0.f, own1 = 0.f;
    const float* xwp = &d_xw0[b * 128][0];
    float xwA = xwp[rowA], xwB = xwp[rowB];
    for (int t = 0; t < 128; t++) {
        float nxA = 0.f, nxB = 0.f;
        if (t < 127) { nxA = xwp[(t + 1) * 48 + rowA]; nxB = xwp[(t + 1) * 48 + rowB]; }
        // layer 0: lanes<16 hold r locally, lanes>=16 hold z
        float ghA = dot16(whA, h0) + bhA;
        float s = sigt(xwA + ghA);
        float ghB = dot16(whB, h0) + bhB;
        float n = tanha(fmaf(s, ghB, xwB));           // lanes<16
        float z = __shfl_sync(FULL, s, 16 + j);
        float hn = fmaf(z, own0 - n, n);              // lanes<16
        float no0 = own0;
#pragma unroll
        for (int k = 0; k < 16; k++) {
            float v = __shfl_sync(FULL, hn, k);
            h0[k] = v;
            if (k == j) no0 = v;
        }
        own0 = no0;
        // layer 1
        float xwA1 = dot16(wiA1, h0) + biA1;
        float ghA1 = dot16(whA1, h1) + bhA1;
        float s1 = sigt(xwA1 + ghA1);
        float xwB1 = dot16(wiB1, h0) + biB1;
        float ghB1 = dot16(whB1, h1) + bhB1;
        float n1 = tanha(fmaf(s1, ghB1, xwB1));
        float z1 = __shfl_sync(FULL, s1, 16 + j);
        float hn1 = fmaf(z1, own1 - n1, n1);
        float no1 = own1;
#pragma unroll
        for (int k = 0; k < 16; k++) {
            float v = __shfl_sync(FULL, hn1, k);
            h1[k] = v;
            if (k == j) no1 = v;
        }
        own1 = no1;
        xwA = nxA; xwB = nxB;
    }
    if (lane < 16) d_Zlast[b][lane] = h1[lane];
}

// ---------------- K7: decoder expert layer-1 + BN + ELU + gate-weighting ----------------
__global__ void __launch_bounds__(256) dec1_kernel(
    const float* __restrict__ Remote,
    const float* __restrict__ w1, const float* __restrict__ b1,
    const float* __restrict__ gmd, const float* __restrict__ btmd)
{
    __shared__ float w1s[2176];
    __shared__ float sb1[128];
    __shared__ float sh[64][17];
    __shared__ float sa[16], sc[16];
    int tid = threadIdx.x;
    for (int i = tid; i < 2176; i += 256) w1s[i] = w1[i];
    if (tid < 128) sb1[tid] = b1[tid];
    int b = tid >> 2, q = tid & 3;
    float x[17];
#pragma unroll
    for (int k = 0; k < 16; k++) x[k] = d_Zlast[b][k];
    x[16] = Remote[(size_t)b * 16896 + 127 * 132 + 131];
    const float* gp = &d_gate[0][0][0][0];
    float om[8];
#pragma unroll
    for (int e = 0; e < 8; e++) om[e] = gp[(size_t)(8192 + b * 128 + 127) * 8 + e];
    __syncthreads();
    float h[4];
#pragma unroll
    for (int hq = 0; hq < 4; hq++) {
        int hh = q * 4 + hq;
        float acc = 0.f;
#pragma unroll 1
        for (int e = 0; e < 8; e++) {
            float a = sb1[e * 16 + hh];
#pragma unroll
            for (int i = 0; i < 17; i++) a = fmaf(x[i], w1s[e * 272 + i * 16 + hh], a);
            acc = fmaf(om[e], a, acc);
        }
        h[hq] = acc;
        sh[b][hh] = acc;
    }
    __syncthreads();
    if (tid < 16) {
        float s = 0.f, s2 = 0.f;
#pragma unroll 8
        for (int bb = 0; bb < 64; bb++) {
            float v = sh[bb][tid];
            s += v; s2 = fmaf(v, v, s2);
        }
        float m = s * (1.f / 64.f);
        float vv = s2 * (1.f / 64.f) - m * m;
        float a = gmd[tid] * rsqrtf(vv + BNEPS);
        sa[tid] = a;
        sc[tid] = btmd[tid] - m * a;
    }
    __syncthreads();
#pragma unroll
    for (int hq = 0; hq < 4; hq++) {
        int hh = q * 4 + hq;
        float t = sa[hh] * h[hq] + sc[hh];
        float hv = t > 0.f ? t : (__expf(t) - 1.f);
#pragma unroll
        for (int e = 0; e < 8; e++) d_q[b][e * 16 + hh] = om[e] * hv;
    }
}

// ---------------- K8: decoder layer-2 -> output ----------------
__global__ void __launch_bounds__(128) dec2_kernel(
    const float* __restrict__ w2, const float* __restrict__ b2,
    float* __restrict__ out)
{
    int b = blockIdx.x, o = threadIdx.x;
    __shared__ float sq[128];
    sq[o] = d_q[b][o];
    __syncthreads();
    const float* gp = &d_gate[0][0][0][0];
    float acc = 0.f;
#pragma unroll 4
    for (int k = 0; k < 128; k++) acc = fmaf(sq[k], w2[k * 128 + o], acc);
#pragma unroll
    for (int e = 0; e < 8; e++)
        acc = fmaf(gp[(size_t)(8192 + b * 128 + 127) * 8 + e], b2[e * 128 + o], acc);
    out[b * 128 + o] = acc;
}

// ---------------- host ----------------
extern "C" void kernel_launch(void* const* d_in, const int* in_sizes, int n_in,
                              void* d_out, int out_size) {
    const float* Local = (const float*)d_in[0];
    const float* Remote = (const float*)d_in[1];
    const float *gWih0, *gWhh0, *gbih0, *gbhh0, *gWih1, *gWhh1, *gbih1, *gbhh1;
    const float *aew1, *aeb1, *aew2, *aeb2, *aeg, *aebt;
    const float *mdw1, *mdb1, *mdw2, *mdb2, *mdg, *mdbt;
    const float *mWih0, *mWhh0, *mbih0, *mbhh0, *mWih1, *mWhh1, *mbih1, *mbhh1;
#define FP(i) ((const float*)d_in[(i)])
    if (in_sizes[2] == 72) {
        gWih0 = FP(2); gWhh0 = FP(3); gbih0 = FP(4); gbhh0 = FP(5);
        gWih1 = FP(6); gWhh1 = FP(7); gbih1 = FP(8); gbhh1 = FP(9);
        int ae, m;
        if (in_sizes[10] == 16384) { ae = 10; m = 22; }   // signature order
        else                       { m = 10; ae = 18; }   // setup_inputs dict order
        aew1 = FP(ae + 0); aeb1 = FP(ae + 1); aew2 = FP(ae + 2);
        aeb2 = FP(ae + 3); aeg  = FP(ae + 4); aebt = FP(ae + 5);
        mdw1 = FP(ae + 6); mdb1 = FP(ae + 7); mdw2 = FP(ae + 8);
        mdb2 = FP(ae + 9); mdg  = FP(ae + 10); mdbt = FP(ae + 11);
        mWih0 = FP(m + 0); mWhh0 = FP(m + 1); mbih0 = FP(m + 2); mbhh0 = FP(m + 3);
        mWih1 = FP(m + 4); mWhh1 = FP(m + 5); mbih1 = FP(m + 6); mbhh1 = FP(m + 7);
    } else {
        // alphabetical fallback
        aeb1 = FP(2); aeb2 = FP(3); aebt = FP(4); aeg = FP(5); aew1 = FP(6); aew2 = FP(7);
        gWhh0 = FP(8); gWhh1 = FP(9); gWih0 = FP(10); gWih1 = FP(11);
        gbhh0 = FP(12); gbhh1 = FP(13); gbih0 = FP(14); gbih1 = FP(15);
        mWhh0 = FP(16); mWhh1 = FP(17); mWih0 = FP(18); mWih1 = FP(19);
        mbhh0 = FP(20); mbhh1 = FP(21); mbih0 = FP(22); mbih1 = FP(23);
        mdb1 = FP(24); mdb2 = FP(25); mdbt = FP(26); mdg = FP(27); mdw1 = FP(28); mdw2 = FP(29);
    }
#undef FP
    float* out = (float*)d_out;

    gate_kernel<<<16, 128>>>(Local, Remote, gWih0, gWhh0, gbih0, gbhh0,
                             gWih1, gWhh1, gbih1, gbhh1);
    expert1_kernel<<<dim3(256, 2), 128>>>(Local, Remote, aew1, aeb1);
    bnfin_kernel<<<1, 1024>>>(aeg, aebt);
    zxw_kernel<<<64, 128>>>(aew2, aeb2, mWih0, mbih0);
    mgru_kernel<<<64, 32>>>(mWhh0, mbhh0, mWih1, mbih1, mWhh1, mbhh1);
    dec1_kernel<<<1, 256>>>(Remote, mdw1, mdb1, mdg, mdbt);
    dec2_kernel<<<64, 128>>>(mdw2, mdb2, out);
}

// round 6
// speedup vs baseline: 2.2306x; 1.1207x over previous
#include <cuda_runtime.h>

#define FULL 0xffffffffu
#define BNEPS 1e-5f

// ---------------- scratch (device globals; allocation is forbidden) ----------------
__device__ float d_gate[2][64][128][8];   // softmax gates (side, b, t, e)
__device__ float d_hpre[2][8192][16];     // expert layer-1 pre-BN hidden
__device__ float d_part[2][256][32];      // per-block BN partial sums [sum(16) | sumsq(16)]
__device__ float d_bn[2][2][16];          // per-side BN scale/shift
__device__ float d_xw0[8192][48];         // precomputed main-GRU layer0 input projection
__device__ float d_Zlast[64][16];         // main GRU final hidden
__device__ float d_q[64][128];            // decoder gated hidden (om[e]*h[hh])

// ---------------- fast math ----------------
__device__ __forceinline__ float tanha(float x) {
    float y;
    asm("tanh.approx.f32 %0, %1;" : "=f"(y) : "f"(x));
    return y;
}
__device__ __forceinline__ float sigt(float x) {          // sigmoid via tanh
    return fmaf(tanha(0.5f * x), 0.5f, 0.5f);
}
__device__ __forceinline__ unsigned long long pack2(float x, float y) {
    unsigned long long r;
    asm("mov.b64 %0, {%1, %2};" : "=l"(r) : "f"(x), "f"(y));
    return r;
}
__device__ __forceinline__ void unpack2(unsigned long long v, float& x, float& y) {
    asm("mov.b64 {%0, %1}, %2;" : "=f"(x), "=f"(y) : "l"(v));
}
__device__ __forceinline__ unsigned long long fma2(unsigned long long a,
                                                   unsigned long long b,
                                                   unsigned long long c) {
    unsigned long long d;
    asm("fma.rn.f32x2 %0, %1, %2, %3;" : "=l"(d) : "l"(a), "l"(b), "l"(c));
    return d;
}
__device__ __forceinline__ float dot8(const float* w, const float* h) {
    float a0 = fmaf(w[1], h[1], w[0] * h[0]);
    float a1 = fmaf(w[3], h[3], w[2] * h[2]);
    float a2 = fmaf(w[5], h[5], w[4] * h[4]);
    float a3 = fmaf(w[7], h[7], w[6] * h[6]);
    return (a0 + a1) + (a2 + a3);
}
__device__ __forceinline__ float dot16(const float* w, const float* h) {
    float a0 = fmaf(w[1], h[1], w[0] * h[0]);
    a0 = fmaf(w[2], h[2], a0); a0 = fmaf(w[3], h[3], a0);
    float a1 = fmaf(w[5], h[5], w[4] * h[4]);
    a1 = fmaf(w[6], h[6], a1); a1 = fmaf(w[7], h[7], a1);
    float a2 = fmaf(w[9], h[9], w[8] * h[8]);
    a2 = fmaf(w[10], h[10], a2); a2 = fmaf(w[11], h[11], a2);
    float a3 = fmaf(w[13], h[13], w[12] * h[12]);
    a3 = fmaf(w[14], h[14], a3); a3 = fmaf(w[15], h[15], a3);
    return (a0 + a1) + (a2 + a3);
}

// ---------------- K2: gate GRU — lane owns r,z,n rows; lanes 0-7=Local, 8-15=Remote ----------------
__global__ void __launch_bounds__(128) gate_kernel(
    const float* __restrict__ Local, const float* __restrict__ Remote,
    const float* __restrict__ Wih0, const float* __restrict__ Whh0,
    const float* __restrict__ bih0, const float* __restrict__ bhh0,
    const float* __restrict__ Wih1, const float* __restrict__ Whh1,
    const float* __restrict__ bih1, const float* __restrict__ bhh1)
{
    int b = blockIdx.x * 4 + (threadIdx.x >> 5);      // 0..63
    int lane = threadIdx.x & 31;
    int sub = (lane >> 3) & 1;                        // 0 = Local, 1 = Remote
    int j = lane & 7;
    int rz = 8 + j, rn = 16 + j;

    float wir[3], wiz[3], win[3];
#pragma unroll
    for (int k = 0; k < 3; k++) {
        wir[k] = Wih0[j * 3 + k];
        wiz[k] = Wih0[rz * 3 + k];
        win[k] = Wih0[rn * 3 + k];
    }
    float bir = bih0[j], biz = bih0[rz], bin = bih0[rn];
    float whr[8], whz[8], whn[8], wir1[8], wiz1[8], win1[8], whr1[8], whz1[8], whn1[8];
#pragma unroll
    for (int k = 0; k < 8; k++) {
        whr[k] = Whh0[j * 8 + k];  whz[k] = Whh0[rz * 8 + k];  whn[k] = Whh0[rn * 8 + k];
        wir1[k] = Wih1[j * 8 + k]; wiz1[k] = Wih1[rz * 8 + k]; win1[k] = Wih1[rn * 8 + k];
        whr1[k] = Whh1[j * 8 + k]; whz1[k] = Whh1[rz * 8 + k]; whn1[k] = Whh1[rn * 8 + k];
    }
    float bhr = bhh0[j], bhz = bhh0[rz], bhn = bhh0[rn];
    float bir1 = bih1[j], biz1 = bih1[rz], bin1 = bih1[rn];
    float bhr1 = bhh1[j], bhz1 = bhh1[rz], bhn1 = bhh1[rn];

    float h0[8], h1[8];
#pragma unroll
    for (int k = 0; k < 8; k++) { h0[k] = 0.f; h1[k] = 0.f; }

    const float* xb = (sub ? Remote : Local) + (size_t)b * 16896 + 128;
    float* outp = &d_gate[sub][b][0][0];
    float4 xc = *(const float4*)xb;
    int base = lane & 8;

    for (int t = 0; t < 128; t++) {
        float4 xn = xc;
        if (t < 127) xn = *(const float4*)(xb + (size_t)(t + 1) * 132);
        // ---- layer 0 ----
        float xwr = fmaf(xc.z, wir[2], fmaf(xc.y, wir[1], fmaf(xc.x, wir[0], bir)));
        float xwz = fmaf(xc.z, wiz[2], fmaf(xc.y, wiz[1], fmaf(xc.x, wiz[0], biz)));
        float xwn = fmaf(xc.z, win[2], fmaf(xc.y, win[1], fmaf(xc.x, win[0], bin)));
        float ghr = dot8(whr, h0) + bhr;
        float ghz = dot8(whz, h0) + bhz;
        float ghn = dot8(whn, h0) + bhn;
        float r = sigt(xwr + ghr);
        float z = sigt(xwz + ghz);
        float n = tanha(fmaf(r, ghn, xwn));
        float hn = fmaf(z, h0[j] - n, n);
#pragma unroll
        for (int k = 0; k < 8; k++) h0[k] = __shfl_sync(FULL, hn, base + k);
        // ---- layer 1 ----
        float xwr1 = dot8(wir1, h0) + bir1;
        float xwz1 = dot8(wiz1, h0) + biz1;
        float xwn1 = dot8(win1, h0) + bin1;
        float ghr1 = dot8(whr1, h1) + bhr1;
        float ghz1 = dot8(whz1, h1) + bhz1;
        float ghn1 = dot8(whn1, h1) + bhn1;
        float r1 = sigt(xwr1 + ghr1);
        float z1 = sigt(xwz1 + ghz1);
        float n1 = tanha(fmaf(r1, ghn1, xwn1));
        float hn1 = fmaf(z1, h1[j] - n1, n1);
#pragma unroll
        for (int k = 0; k < 8; k++) h1[k] = __shfl_sync(FULL, hn1, base + k);
        // ---- softmax over 8 (h1 in (-1,1): no max shift) ----
        float ev = __expf(hn1);
        float ss = ev;
        ss += __shfl_xor_sync(FULL, ss, 1);
        ss += __shfl_xor_sync(FULL, ss, 2);
        ss += __shfl_xor_sync(FULL, ss, 4);
        if (lane < 16) outp[t * 8 + j] = __fdividef(ev, ss);
        xc = xn;
    }
}

// ---------------- K3: expert layer-1 GEMM (f32x2) + gate combine + BN partials ----------------
__global__ void __launch_bounds__(128) expert1_kernel(
    const float* __restrict__ Local, const float* __restrict__ Remote,
    const float* __restrict__ w1, const float* __restrict__ b1)
{
    int side = blockIdx.y;
    const float* src = side ? Remote : Local;
    int w = threadIdx.x >> 5, lane = threadIdx.x & 31;
    int n0 = blockIdx.x * 32 + w * 8;

    __shared__ __align__(16) float2 xs2[4][8][128];   // duplicated x for LDS.64 -> (x,x)
    __shared__ float swp[4][32];

#pragma unroll
    for (int s = 0; s < 8; s++) {
        int n = n0 + s;
        int bb = n >> 7, t = n & 127;
        float4 v = *(const float4*)(src + (size_t)bb * 16896 + t * 132 + lane * 4);
        xs2[w][s][lane * 4 + 0] = make_float2(v.x, v.x);
        xs2[w][s][lane * 4 + 1] = make_float2(v.y, v.y);
        xs2[w][s][lane * 4 + 2] = make_float2(v.z, v.z);
        xs2[w][s][lane * 4 + 3] = make_float2(v.w, v.w);
    }
    int e = lane >> 2, hq = lane & 3;
    const float* gp = &d_gate[0][0][0][0];
    float gg[8];
#pragma unroll
    for (int s = 0; s < 8; s++) gg[s] = gp[((size_t)side * 8192 + n0 + s) * 8 + e];
    __syncthreads();

    unsigned long long a01[8], a23[8];
#pragma unroll
    for (int s = 0; s < 8; s++) { a01[s] = 0ull; a23[s] = 0ull; }

    const float* wbase = w1 + (size_t)e * 2048 + hq * 4;   // (e*128+i)*16 + 4*hq
#pragma unroll 4
    for (int i = 0; i < 128; i++) {
        float4 wv = *(const float4*)(wbase + i * 16);
        unsigned long long w01 = pack2(wv.x, wv.y);
        unsigned long long w23 = pack2(wv.z, wv.w);
#pragma unroll
        for (int s = 0; s < 8; s++) {
            unsigned long long xp = *(const unsigned long long*)&xs2[w][s][i];
            a01[s] = fma2(w01, xp, a01[s]);
            a23[s] = fma2(w23, xp, a23[s]);
        }
    }
    float4 bq = *(const float4*)(b1 + e * 16 + hq * 4);
    float vv[8][4];
#pragma unroll
    for (int s = 0; s < 8; s++) {
        float v0, v1, v2, v3;
        unpack2(a01[s], v0, v1);
        unpack2(a23[s], v2, v3);
        v0 = (v0 + bq.x) * gg[s]; v1 = (v1 + bq.y) * gg[s];
        v2 = (v2 + bq.z) * gg[s]; v3 = (v3 + bq.w) * gg[s];
#pragma unroll
        for (int o = 4; o < 32; o <<= 1) {
            v0 += __shfl_xor_sync(FULL, v0, o);
            v1 += __shfl_xor_sync(FULL, v1, o);
            v2 += __shfl_xor_sync(FULL, v2, o);
            v3 += __shfl_xor_sync(FULL, v3, o);
        }
        vv[s][0] = v0; vv[s][1] = v1; vv[s][2] = v2; vv[s][3] = v3;
    }
    if (lane < 4) {
        float sx[4] = {0, 0, 0, 0}, sq[4] = {0, 0, 0, 0};
#pragma unroll
        for (int s = 0; s < 8; s++) {
            *(float4*)&d_hpre[side][n0 + s][lane * 4] =
                make_float4(vv[s][0], vv[s][1], vv[s][2], vv[s][3]);
#pragma unroll
            for (int c = 0; c < 4; c++) {
                sx[c] += vv[s][c];
                sq[c] = fmaf(vv[s][c], vv[s][c], sq[c]);
            }
        }
#pragma unroll
        for (int c = 0; c < 4; c++) {
            swp[w][lane * 4 + c] = sx[c];
            swp[w][16 + lane * 4 + c] = sq[c];
        }
    }
    __syncthreads();
    if (threadIdx.x < 32) {
        float acc = swp[0][threadIdx.x] + swp[1][threadIdx.x] +
                    swp[2][threadIdx.x] + swp[3][threadIdx.x];
        d_part[side][blockIdx.x][threadIdx.x] = acc;
    }
}

// ---------------- K4: BN finalize (parallel reduction) ----------------
__global__ void __launch_bounds__(1024) bnfin_kernel(
    const float* __restrict__ ae_g, const float* __restrict__ ae_bt)
{
    __shared__ float sp[2][32][16];
    int t = threadIdx.x;                     // 1024
    int side = t >> 9, rem = t & 511;
    int ch = rem & 31, chunk = rem >> 5;     // chunk 0..15
    float s = 0.f;
#pragma unroll
    for (int k = 0; k < 16; k++) s += d_part[side][chunk * 16 + k][ch];
    sp[side][ch][chunk] = s;
    __syncthreads();
    if (t < 32) {
        int sd = t >> 4, c = t & 15;
        float su = 0.f, sq = 0.f;
#pragma unroll
        for (int k = 0; k < 16; k++) {
            su += sp[sd][c][k];
            sq += sp[sd][16 + c][k];
        }
        float m = su * (1.f / 8192.f);
        float v = sq * (1.f / 8192.f) - m * m;
        float a = ae_g[c] * rsqrtf(v + BNEPS);
        d_bn[sd][0][c] = a;
        d_bn[sd][1][c] = ae_bt[c] - m * a;
    }
}

// ---------------- K5: fused BN+ELU + gated-combine GEMM + projection ----------------
// block = 128 threads, 32 samples. hg[n][e*16+hh] = omL*hL + omR*hR; Z = hg @ w2flat; xw0 = Z @ mWih0^T
__global__ void __launch_bounds__(128) fuse2_kernel(
    const float* __restrict__ w2, const float* __restrict__ b2,
    const float* __restrict__ mWih0, const float* __restrict__ mbih0)
{
    __shared__ float sh[32][33];          // ELU'd hidden: [s][0..15]=L, [16..31]=R
    __shared__ __align__(16) float hg[32][132];
    __shared__ __align__(16) float w2t[16][132];   // transposed w2: [o][k]
    __shared__ float b2s[128];
    __shared__ float gl[32][8], gr[32][8];
    __shared__ float zs[32][17];
    __shared__ __align__(16) float mWs[768];
    __shared__ float mbs[48];
    int t = threadIdx.x;
    int n0 = blockIdx.x * 32;
    const float* gp = &d_gate[0][0][0][0];

#pragma unroll
    for (int i = 0; i < 16; i++) {
        int idx = i * 128 + t;           // 2048
        int o = idx >> 7, k = idx & 127;
        w2t[o][k] = w2[k * 16 + o];
    }
    b2s[t] = b2[t];
#pragma unroll
    for (int i = 0; i < 6; i++) mWs[i * 128 + t] = mWih0[i * 128 + t];
    if (t < 48) mbs[t] = mbih0[t];
#pragma unroll
    for (int i = 0; i < 4; i++) {
        int idx = i * 128 + t;           // 512 = 32 samples x 16 gates
        int s = idx >> 4, c = idx & 15;
        float v = gp[((size_t)((c >> 3) * 8192) + n0 + s) * 8 + (c & 7)];
        if (c < 8) gl[s][c] = v; else gr[s][c - 8] = v;
    }
#pragma unroll
    for (int i = 0; i < 8; i++) {
        int idx = i * 128 + t;           // 1024 = 32 x 32
        int s = idx >> 5, c = idx & 31;
        int side = c >> 4, ch = c & 15;
        float a = d_bn[side][0][ch] * d_hpre[side][n0 + s][ch] + d_bn[side][1][ch];
        sh[s][c] = a > 0.f ? a : (__expf(a) - 1.f);
    }
    __syncthreads();
    {
        int e = t >> 4, hh = t & 15;
#pragma unroll 4
        for (int s = 0; s < 32; s++)
            hg[s][t] = fmaf(gl[s][e], sh[s][hh], gr[s][e] * sh[s][16 + hh]);
    }
    __syncthreads();
    {
        int o = t & 15, sg = t >> 4;      // sg 0..7, 4 samples each
        int s0 = sg * 4;
        float a0 = 0.f, a1 = 0.f, a2 = 0.f, a3 = 0.f;
#pragma unroll 4
        for (int k = 0; k < 128; k += 4) {
            float4 wv = *(const float4*)&w2t[o][k];
            float4 g0 = *(const float4*)&hg[s0 + 0][k];
            float4 g1 = *(const float4*)&hg[s0 + 1][k];
            float4 g2 = *(const float4*)&hg[s0 + 2][k];
            float4 g3 = *(const float4*)&hg[s0 + 3][k];
            a0 = fmaf(g0.x, wv.x, a0); a0 = fmaf(g0.y, wv.y, a0);
            a0 = fmaf(g0.z, wv.z, a0); a0 = fmaf(g0.w, wv.w, a0);
            a1 = fmaf(g1.x, wv.x, a1); a1 = fmaf(g1.y, wv.y, a1);
            a1 = fmaf(g1.z, wv.z, a1); a1 = fmaf(g1.w, wv.w, a1);
            a2 = fmaf(g2.x, wv.x, a2); a2 = fmaf(g2.y, wv.y, a2);
            a2 = fmaf(g2.z, wv.z, a2); a2 = fmaf(g2.w, wv.w, a2);
            a3 = fmaf(g3.x, wv.x, a3); a3 = fmaf(g3.y, wv.y, a3);
            a3 = fmaf(g3.z, wv.z, a3); a3 = fmaf(g3.w, wv.w, a3);
        }
        float accs[4] = {a0, a1, a2, a3};
#pragma unroll
        for (int ss = 0; ss < 4; ss++) {
            float bsum = accs[ss];
#pragma unroll
            for (int e = 0; e < 8; e++)
                bsum = fmaf(gl[s0 + ss][e] + gr[s0 + ss][e], b2s[e * 16 + o], bsum);
            zs[s0 + ss][o] = bsum;
        }
    }
    __syncthreads();
    {
        int s = t >> 2, q = t & 3;        // 12 outputs per thread
        float z[16];
#pragma unroll
        for (int h = 0; h < 16; h++) z[h] = zs[s][h];
#pragma unroll
        for (int gi = 0; gi < 12; gi++) {
            int g = q * 12 + gi;
            float acc = mbs[g];
#pragma unroll
            for (int h = 0; h < 16; h++) acc = fmaf(z[h], mWs[g * 16 + h], acc);
            d_xw0[n0 + s][g] = acc;
        }
    }
}

// ---------------- K6: main GRU — lane owns r,z,n rows; 2 samples per warp ----------------
__global__ void __launch_bounds__(128) mgru_kernel(
    const float* __restrict__ Whh0, const float* __restrict__ bhh0_,
    const float* __restrict__ Wih1, const float* __restrict__ bih1_,
    const float* __restrict__ Whh1, const float* __restrict__ bhh1_)
{
    int warp = blockIdx.x * 4 + (threadIdx.x >> 5);   // 0..31
    int lane = threadIdx.x & 31;
    int sub = lane >> 4, j = lane & 15;
    int b = warp * 2 + sub;
    int rz = 16 + j, rn = 32 + j;

    float whr[16], whz[16], whn[16], wir1[16], wiz1[16], win1[16], whr1[16], whz1[16], whn1[16];
#pragma unroll
    for (int k = 0; k < 16; k++) {
        whr[k] = Whh0[j * 16 + k];  whz[k] = Whh0[rz * 16 + k];  whn[k] = Whh0[rn * 16 + k];
        wir1[k] = Wih1[j * 16 + k]; wiz1[k] = Wih1[rz * 16 + k]; win1[k] = Wih1[rn * 16 + k];
        whr1[k] = Whh1[j * 16 + k]; whz1[k] = Whh1[rz * 16 + k]; whn1[k] = Whh1[rn * 16 + k];
    }
    float bhr = bhh0_[j], bhz = bhh0_[rz], bhn = bhh0_[rn];
    float bir1 = bih1_[j], biz1 = bih1_[rz], bin1 = bih1_[rn];
    float bhr1 = bhh1_[j], bhz1 = bhh1_[rz], bhn1 = bhh1_[rn];

    float h0[16], h1[16];
#pragma unroll
    for (int k = 0; k < 16; k++) { h0[k] = 0.f; h1[k] = 0.f; }

    const float* xwp = &d_xw0[b * 128][0];
    float xr = xwp[j], xz = xwp[rz], xn = xwp[rn];
    int base = lane & 16;

    for (int t = 0; t < 128; t++) {
        float pr = 0.f, pz = 0.f, pn = 0.f;
        if (t < 127) {
            pr = xwp[(t + 1) * 48 + j];
            pz = xwp[(t + 1) * 48 + rz];
            pn = xwp[(t + 1) * 48 + rn];
        }
        // ---- layer 0 ----
        float ghr = dot16(whr, h0) + bhr;
        float ghz = dot16(whz, h0) + bhz;
        float ghn = dot16(whn, h0) + bhn;
        float r = sigt(xr + ghr);
        float z = sigt(xz + ghz);
        float n = tanha(fmaf(r, ghn, xn));
        float hn = fmaf(z, h0[j] - n, n);
#pragma unroll
        for (int k = 0; k < 16; k++) h0[k] = __shfl_sync(FULL, hn, base + k);
        // ---- layer 1 ----
        float xr1 = dot16(wir1, h0) + bir1;
        float xz1 = dot16(wiz1, h0) + biz1;
        float xn1 = dot16(win1, h0) + bin1;
        float ghr1 = dot16(whr1, h1) + bhr1;
        float ghz1 = dot16(whz1, h1) + bhz1;
        float ghn1 = dot16(whn1, h1) + bhn1;
        float r1 = sigt(xr1 + ghr1);
        float z1 = sigt(xz1 + ghz1);
        float n1 = tanha(fmaf(r1, ghn1, xn1));
        float hn1 = fmaf(z1, h1[j] - n1, n1);
#pragma unroll
        for (int k = 0; k < 16; k++) h1[k] = __shfl_sync(FULL, hn1, base + k);
        xr = pr; xz = pz; xn = pn;
    }
    d_Zlast[b][j] = h1[j];
}

// ---------------- K7: decoder expert layer-1 + BN + ELU + gate-weighting ----------------
__global__ void __launch_bounds__(256) dec1_kernel(
    const float* __restrict__ Remote,
    const float* __restrict__ w1, const float* __restrict__ b1,
    const float* __restrict__ gmd, const float* __restrict__ btmd)
{
    __shared__ float w1s[2176];
    __shared__ float sb1[128];
    __shared__ float sh[64][17];
    __shared__ float sa[16], sc[16];
    int tid = threadIdx.x;
    for (int i = tid; i < 2176; i += 256) w1s[i] = w1[i];
    if (tid < 128) sb1[tid] = b1[tid];
    int b = tid >> 2, q = tid & 3;
    float x[17];
#pragma unroll
    for (int k = 0; k < 16; k++) x[k] = d_Zlast[b][k];
    x[16] = Remote[(size_t)b * 16896 + 127 * 132 + 131];
    const float* gp = &d_gate[0][0][0][0];
    float om[8];
#pragma unroll
    for (int e = 0; e < 8; e++) om[e] = gp[(size_t)(8192 + b * 128 + 127) * 8 + e];
    __syncthreads();
    float h[4];
#pragma unroll
    for (int hq = 0; hq < 4; hq++) {
        int hh = q * 4 + hq;
        float acc = 0.f;
#pragma unroll 1
        for (int e = 0; e < 8; e++) {
            float a = sb1[e * 16 + hh];
#pragma unroll
            for (int i = 0; i < 17; i++) a = fmaf(x[i], w1s[e * 272 + i * 16 + hh], a);
            acc = fmaf(om[e], a, acc);
        }
        h[hq] = acc;
        sh[b][hh] = acc;
    }
    __syncthreads();
    if (tid < 16) {
        float s = 0.f, s2 = 0.f;
#pragma unroll 8
        for (int bb = 0; bb < 64; bb++) {
            float v = sh[bb][tid];
            s += v; s2 = fmaf(v, v, s2);
        }
        float m = s * (1.f / 64.f);
        float vv = s2 * (1.f / 64.f) - m * m;
        float a = gmd[tid] * rsqrtf(vv + BNEPS);
        sa[tid] = a;
        sc[tid] = btmd[tid] - m * a;
    }
    __syncthreads();
#pragma unroll
    for (int hq = 0; hq < 4; hq++) {
        int hh = q * 4 + hq;
        float t = sa[hh] * h[hq] + sc[hh];
        float hv = t > 0.f ? t : (__expf(t) - 1.f);
#pragma unroll
        for (int e = 0; e < 8; e++) d_q[b][e * 16 + hh] = om[e] * hv;
    }
}

// ---------------- K8: decoder layer-2 -> output ----------------
__global__ void __launch_bounds__(128) dec2_kernel(
    const float* __restrict__ w2, const float* __restrict__ b2,
    float* __restrict__ out)
{
    int b = blockIdx.x, o = threadIdx.x;
    __shared__ float sq[128];
    sq[o] = d_q[b][o];
    __syncthreads();
    const float* gp = &d_gate[0][0][0][0];
    float acc = 0.f;
#pragma unroll 4
    for (int k = 0; k < 128; k++) acc = fmaf(sq[k], w2[k * 128 + o], acc);
#pragma unroll
    for (int e = 0; e < 8; e++)
        acc = fmaf(gp[(size_t)(8192 + b * 128 + 127) * 8 + e], b2[e * 128 + o], acc);
    out[b * 128 + o] = acc;
}

// ---------------- host ----------------
extern "C" void kernel_launch(void* const* d_in, const int* in_sizes, int n_in,
                              void* d_out, int out_size) {
    const float* Local = (const float*)d_in[0];
    const float* Remote = (const float*)d_in[1];
    const float *gWih0, *gWhh0, *gbih0, *gbhh0, *gWih1, *gWhh1, *gbih1, *gbhh1;
    const float *aew1, *aeb1, *aew2, *aeb2, *aeg, *aebt;
    const float *mdw1, *mdb1, *mdw2, *mdb2, *mdg, *mdbt;
    const float *mWih0, *mWhh0, *mbih0, *mbhh0, *mWih1, *mWhh1, *mbih1, *mbhh1;
#define FP(i) ((const float*)d_in[(i)])
    if (in_sizes[2] == 72) {
        gWih0 = FP(2); gWhh0 = FP(3); gbih0 = FP(4); gbhh0 = FP(5);
        gWih1 = FP(6); gWhh1 = FP(7); gbih1 = FP(8); gbhh1 = FP(9);
        int ae, m;
        if (in_sizes[10] == 16384) { ae = 10; m = 22; }   // signature order
        else                       { m = 10; ae = 18; }   // setup_inputs dict order
        aew1 = FP(ae + 0); aeb1 = FP(ae + 1); aew2 = FP(ae + 2);
        aeb2 = FP(ae + 3); aeg  = FP(ae + 4); aebt = FP(ae + 5);
        mdw1 = FP(ae + 6); mdb1 = FP(ae + 7); mdw2 = FP(ae + 8);
        mdb2 = FP(ae + 9); mdg  = FP(ae + 10); mdbt = FP(ae + 11);
        mWih0 = FP(m + 0); mWhh0 = FP(m + 1); mbih0 = FP(m + 2); mbhh0 = FP(m + 3);
        mWih1 = FP(m + 4); mWhh1 = FP(m + 5); mbih1 = FP(m + 6); mbhh1 = FP(m + 7);
    } else {
        // alphabetical fallback
        aeb1 = FP(2); aeb2 = FP(3); aebt = FP(4); aeg = FP(5); aew1 = FP(6); aew2 = FP(7);
        gWhh0 = FP(8); gWhh1 = FP(9); gWih0 = FP(10); gWih1 = FP(11);
        gbhh0 = FP(12); gbhh1 = FP(13); gbih0 = FP(14); gbih1 = FP(15);
        mWhh0 = FP(16); mWhh1 = FP(17); mWih0 = FP(18); mWih1 = FP(19);
        mbhh0 = FP(20); mbhh1 = FP(21); mbih0 = FP(22); mbih1 = FP(23);
        mdb1 = FP(24); mdb2 = FP(25); mdbt = FP(26); mdg = FP(27); mdw1 = FP(28); mdw2 = FP(29);
    }
#undef FP
    float* out = (float*)d_out;

    gate_kernel<<<16, 128>>>(Local, Remote, gWih0, gWhh0, gbih0, gbhh0,
                             gWih1, gWhh1, gbih1, gbhh1);
    expert1_kernel<<<dim3(256, 2), 128>>>(Local, Remote, aew1, aeb1);
    bnfin_kernel<<<1, 1024>>>(aeg, aebt);
    fuse2_kernel<<<256, 128>>>(aew2, aeb2, mWih0, mbih0);
    mgru_kernel<<<8, 128>>>(mWhh0, mbhh0, mWih1, mbih1, mWhh1, mbhh1);
    dec1_kernel<<<1, 256>>>(Remote, mdw1, mdb1, mdg, mdbt);
    dec2_kernel<<<64, 128>>>(mdw2, mdb2, out);
}

// round 7
// speedup vs baseline: 2.4762x; 1.1101x over previous
#include <cuda_runtime.h>

#define FULL 0xffffffffu
#define BNEPS 1e-5f

// ---------------- scratch (device globals; allocation is forbidden) ----------------
__device__ float d_gate[2][64][128][8];   // softmax gates (side, b, t, e)
__device__ float d_y[2][8192][128];       // ungated expert layer-1 outputs [n][e*16+hh]
__device__ float d_hpre[2][8192][16];     // gated expert layer-1 hidden (pre-BN)
__device__ float d_part[2][256][32];      // per-warp BN partial sums [sum(16) | sumsq(16)]
__device__ float d_bn[2][2][16];          // per-side BN scale/shift
__device__ float d_xw0[8192][48];         // precomputed main-GRU layer0 input projection
__device__ float d_Zlast[64][16];         // main GRU final hidden
__device__ float d_q[64][128];            // decoder gated hidden

// ---------------- fast math ----------------
__device__ __forceinline__ float tanha(float x) {
    float y;
    asm("tanh.approx.f32 %0, %1;" : "=f"(y) : "f"(x));
    return y;
}
__device__ __forceinline__ float sigt(float x) {          // sigmoid via tanh
    return fmaf(tanha(0.5f * x), 0.5f, 0.5f);
}
__device__ __forceinline__ unsigned long long pack2(float x, float y) {
    unsigned long long r;
    asm("mov.b64 %0, {%1, %2};" : "=l"(r) : "f"(x), "f"(y));
    return r;
}
__device__ __forceinline__ void unpack2(unsigned long long v, float& x, float& y) {
    asm("mov.b64 {%0, %1}, %2;" : "=f"(x), "=f"(y) : "l"(v));
}
__device__ __forceinline__ unsigned long long fma2(unsigned long long a,
                                                   unsigned long long b,
                                                   unsigned long long c) {
    unsigned long long d;
    asm("fma.rn.f32x2 %0, %1, %2, %3;" : "=l"(d) : "l"(a), "l"(b), "l"(c));
    return d;
}
__device__ __forceinline__ float dot8(const float* w, const float* h) {
    float a0 = fmaf(w[1], h[1], w[0] * h[0]);
    float a1 = fmaf(w[3], h[3], w[2] * h[2]);
    float a2 = fmaf(w[5], h[5], w[4] * h[4]);
    float a3 = fmaf(w[7], h[7], w[6] * h[6]);
    return (a0 + a1) + (a2 + a3);
}
__device__ __forceinline__ float dot16(const float* w, const float* h) {
    float a0 = fmaf(w[1], h[1], w[0] * h[0]);
    a0 = fmaf(w[2], h[2], a0); a0 = fmaf(w[3], h[3], a0);
    float a1 = fmaf(w[5], h[5], w[4] * h[4]);
    a1 = fmaf(w[6], h[6], a1); a1 = fmaf(w[7], h[7], a1);
    float a2 = fmaf(w[9], h[9], w[8] * h[8]);
    a2 = fmaf(w[10], h[10], a2); a2 = fmaf(w[11], h[11], a2);
    float a3 = fmaf(w[13], h[13], w[12] * h[12]);
    a3 = fmaf(w[14], h[14], a3); a3 = fmaf(w[15], h[15], a3);
    return (a0 + a1) + (a2 + a3);
}

// ---------------- K1 mega: blocks 0-15 = gate GRU; blocks 16-527 = ungated expert GEMM ----------------
__global__ void __launch_bounds__(128) mega_kernel(
    const float* __restrict__ Local, const float* __restrict__ Remote,
    const float* __restrict__ Wih0, const float* __restrict__ Whh0,
    const float* __restrict__ bih0, const float* __restrict__ bhh0,
    const float* __restrict__ Wih1, const float* __restrict__ Whh1,
    const float* __restrict__ bih1, const float* __restrict__ bhh1,
    const float* __restrict__ w1, const float* __restrict__ b1)
{
    __shared__ __align__(16) float2 xs2[4][8][128];

    if (blockIdx.x < 16) {
        // ================= gate GRU =================
        int b = blockIdx.x * 4 + (threadIdx.x >> 5);      // 0..63
        int lane = threadIdx.x & 31;
        int sub = (lane >> 3) & 1;                        // 0 = Local, 1 = Remote
        int j = lane & 7;
        int rz = 8 + j, rn = 16 + j;

        float wir[3], wiz[3], win[3];
#pragma unroll
        for (int k = 0; k < 3; k++) {
            wir[k] = Wih0[j * 3 + k];
            wiz[k] = Wih0[rz * 3 + k];
            win[k] = Wih0[rn * 3 + k];
        }
        float bir = bih0[j], biz = bih0[rz], bin = bih0[rn];
        float whr[8], whz[8], whn[8], wir1[8], wiz1[8], win1[8], whr1[8], whz1[8], whn1[8];
#pragma unroll
        for (int k = 0; k < 8; k++) {
            whr[k] = Whh0[j * 8 + k];  whz[k] = Whh0[rz * 8 + k];  whn[k] = Whh0[rn * 8 + k];
            wir1[k] = Wih1[j * 8 + k]; wiz1[k] = Wih1[rz * 8 + k]; win1[k] = Wih1[rn * 8 + k];
            whr1[k] = Whh1[j * 8 + k]; whz1[k] = Whh1[rz * 8 + k]; whn1[k] = Whh1[rn * 8 + k];
        }
        float bhr = bhh0[j], bhz = bhh0[rz], bhn = bhh0[rn];
        float bir1 = bih1[j], biz1 = bih1[rz], bin1 = bih1[rn];
        float bhr1 = bhh1[j], bhz1 = bhh1[rz], bhn1 = bhh1[rn];

        float h0[8], h1[8];
#pragma unroll
        for (int k = 0; k < 8; k++) { h0[k] = 0.f; h1[k] = 0.f; }

        const float* xb = (sub ? Remote : Local) + (size_t)b * 16896 + 128;
        float* outp = &d_gate[sub][b][0][0];
        float4 xc = *(const float4*)xb;
        int base = lane & 8;

        for (int t = 0; t < 128; t++) {
            float4 xn = xc;
            if (t < 127) xn = *(const float4*)(xb + (size_t)(t + 1) * 132);
            // ---- layer 0 ----
            float xwr = fmaf(xc.z, wir[2], fmaf(xc.y, wir[1], fmaf(xc.x, wir[0], bir)));
            float xwz = fmaf(xc.z, wiz[2], fmaf(xc.y, wiz[1], fmaf(xc.x, wiz[0], biz)));
            float xwn = fmaf(xc.z, win[2], fmaf(xc.y, win[1], fmaf(xc.x, win[0], bin)));
            float ghr = dot8(whr, h0) + bhr;
            float ghz = dot8(whz, h0) + bhz;
            float ghn = dot8(whn, h0) + bhn;
            float r = sigt(xwr + ghr);
            float z = sigt(xwz + ghz);
            float n = tanha(fmaf(r, ghn, xwn));
            float hn = fmaf(z, h0[j] - n, n);
#pragma unroll
            for (int k = 0; k < 8; k++) h0[k] = __shfl_sync(FULL, hn, base + k);
            // ---- layer 1 ----
            float xwr1 = dot8(wir1, h0) + bir1;
            float xwz1 = dot8(wiz1, h0) + biz1;
            float xwn1 = dot8(win1, h0) + bin1;
            float ghr1 = dot8(whr1, h1) + bhr1;
            float ghz1 = dot8(whz1, h1) + bhz1;
            float ghn1 = dot8(whn1, h1) + bhn1;
            float r1 = sigt(xwr1 + ghr1);
            float z1 = sigt(xwz1 + ghz1);
            float n1 = tanha(fmaf(r1, ghn1, xwn1));
            float hn1 = fmaf(z1, h1[j] - n1, n1);
#pragma unroll
            for (int k = 0; k < 8; k++) h1[k] = __shfl_sync(FULL, hn1, base + k);
            // ---- softmax over 8 (h1 in (-1,1): no max shift) ----
            float ev = __expf(hn1);
            float ss = ev;
            ss += __shfl_xor_sync(FULL, ss, 1);
            ss += __shfl_xor_sync(FULL, ss, 2);
            ss += __shfl_xor_sync(FULL, ss, 4);
            if (lane < 16) outp[t * 8 + j] = __fdividef(ev, ss);
            xc = xn;
        }
    } else {
        // ================= ungated expert layer-1 GEMM =================
        int bx = blockIdx.x - 16;          // 0..511
        int side = bx >> 8;
        int bq = bx & 255;
        const float* src = side ? Remote : Local;
        int w = threadIdx.x >> 5, lane = threadIdx.x & 31;
        int n0 = bq * 32 + w * 8;

#pragma unroll
        for (int s = 0; s < 8; s++) {
            int n = n0 + s;
            int bb = n >> 7, t = n & 127;
            float4 v = *(const float4*)(src + (size_t)bb * 16896 + t * 132 + lane * 4);
            xs2[w][s][lane * 4 + 0] = make_float2(v.x, v.x);
            xs2[w][s][lane * 4 + 1] = make_float2(v.y, v.y);
            xs2[w][s][lane * 4 + 2] = make_float2(v.z, v.z);
            xs2[w][s][lane * 4 + 3] = make_float2(v.w, v.w);
        }
        int e = lane >> 2, hq = lane & 3;
        __syncthreads();

        unsigned long long a01[8], a23[8];
#pragma unroll
        for (int s = 0; s < 8; s++) { a01[s] = 0ull; a23[s] = 0ull; }

        const float* wbase = w1 + (size_t)e * 2048 + hq * 4;   // (e*128+i)*16 + 4*hq
#pragma unroll 4
        for (int i = 0; i < 128; i++) {
            float4 wv = *(const float4*)(wbase + i * 16);
            unsigned long long w01 = pack2(wv.x, wv.y);
            unsigned long long w23 = pack2(wv.z, wv.w);
#pragma unroll
            for (int s = 0; s < 8; s++) {
                unsigned long long xp = *(const unsigned long long*)&xs2[w][s][i];
                a01[s] = fma2(w01, xp, a01[s]);
                a23[s] = fma2(w23, xp, a23[s]);
            }
        }
        float4 bq4 = *(const float4*)(b1 + e * 16 + hq * 4);
#pragma unroll
        for (int s = 0; s < 8; s++) {
            float v0, v1, v2, v3;
            unpack2(a01[s], v0, v1);
            unpack2(a23[s], v2, v3);
            *(float4*)&d_y[side][n0 + s][lane * 4] =
                make_float4(v0 + bq4.x, v1 + bq4.y, v2 + bq4.z, v3 + bq4.w);
        }
    }
}

// ---------------- K2: apply gates to y -> hpre + BN partials ----------------
// 128 blocks x 128 threads; warp = 32 samples; lane = (e = lane>>2, hq = lane&3)
__global__ void __launch_bounds__(128) combine_kernel()
{
    int w = threadIdx.x >> 5, lane = threadIdx.x & 31;
    int blk = blockIdx.x;                 // 0..127
    int side = blk >> 6;
    int widx = (blk & 63) * 4 + w;        // 0..255 within side
    int nbase = (blk & 63) * 128 + w * 32;
    int e = lane >> 2;
    const float* gp = &d_gate[0][0][0][0];
    float sx0 = 0.f, sx1 = 0.f, sx2 = 0.f, sx3 = 0.f;
    float sq0 = 0.f, sq1 = 0.f, sq2 = 0.f, sq3 = 0.f;
#pragma unroll 4
    for (int s = 0; s < 32; s++) {
        int n = nbase + s;
        float4 y = *(const float4*)&d_y[side][n][lane * 4];
        float g = gp[((size_t)side * 8192 + n) * 8 + e];
        float v0 = y.x * g, v1 = y.y * g, v2 = y.z * g, v3 = y.w * g;
#pragma unroll
        for (int o = 4; o < 32; o <<= 1) {
            v0 += __shfl_xor_sync(FULL, v0, o);
            v1 += __shfl_xor_sync(FULL, v1, o);
            v2 += __shfl_xor_sync(FULL, v2, o);
            v3 += __shfl_xor_sync(FULL, v3, o);
        }
        if (lane < 4) {
            *(float4*)&d_hpre[side][n][lane * 4] = make_float4(v0, v1, v2, v3);
            sx0 += v0; sx1 += v1; sx2 += v2; sx3 += v3;
            sq0 = fmaf(v0, v0, sq0); sq1 = fmaf(v1, v1, sq1);
            sq2 = fmaf(v2, v2, sq2); sq3 = fmaf(v3, v3, sq3);
        }
    }
    if (lane < 4) {
        int c = lane * 4;
        d_part[side][widx][c + 0] = sx0; d_part[side][widx][c + 1] = sx1;
        d_part[side][widx][c + 2] = sx2; d_part[side][widx][c + 3] = sx3;
        d_part[side][widx][16 + c + 0] = sq0; d_part[side][widx][16 + c + 1] = sq1;
        d_part[side][widx][16 + c + 2] = sq2; d_part[side][widx][16 + c + 3] = sq3;
    }
}

// ---------------- K3: BN finalize (parallel reduction) ----------------
__global__ void __launch_bounds__(1024) bnfin_kernel(
    const float* __restrict__ ae_g, const float* __restrict__ ae_bt)
{
    __shared__ float sp[2][32][16];
    int t = threadIdx.x;                     // 1024
    int side = t >> 9, rem = t & 511;
    int ch = rem & 31, chunk = rem >> 5;     // chunk 0..15
    float s = 0.f;
#pragma unroll
    for (int k = 0; k < 16; k++) s += d_part[side][chunk * 16 + k][ch];
    sp[side][ch][chunk] = s;
    __syncthreads();
    if (t < 32) {
        int sd = t >> 4, c = t & 15;
        float su = 0.f, sq = 0.f;
#pragma unroll
        for (int k = 0; k < 16; k++) {
            su += sp[sd][c][k];
            sq += sp[sd][16 + c][k];
        }
        float m = su * (1.f / 8192.f);
        float v = sq * (1.f / 8192.f) - m * m;
        float a = ae_g[c] * rsqrtf(v + BNEPS);
        d_bn[sd][0][c] = a;
        d_bn[sd][1][c] = ae_bt[c] - m * a;
    }
}

// ---------------- K4: fused BN+ELU + gated-combine GEMM + projection ----------------
__global__ void __launch_bounds__(128) fuse2_kernel(
    const float* __restrict__ w2, const float* __restrict__ b2,
    const float* __restrict__ mWih0, const float* __restrict__ mbih0)
{
    __shared__ float sh[32][33];          // ELU'd hidden: [s][0..15]=L, [16..31]=R
    __shared__ __align__(16) float hg[32][132];
    __shared__ __align__(16) float w2t[16][132];   // transposed w2: [o][k]
    __shared__ float b2s[128];
    __shared__ float gl[32][8], gr[32][8];
    __shared__ float zs[32][17];
    __shared__ __align__(16) float mWs[768];
    __shared__ float mbs[48];
    int t = threadIdx.x;
    int n0 = blockIdx.x * 32;
    const float* gp = &d_gate[0][0][0][0];

#pragma unroll
    for (int i = 0; i < 16; i++) {
        int idx = i * 128 + t;           // 2048
        int o = idx >> 7, k = idx & 127;
        w2t[o][k] = w2[k * 16 + o];
    }
    b2s[t] = b2[t];
#pragma unroll
    for (int i = 0; i < 6; i++) mWs[i * 128 + t] = mWih0[i * 128 + t];
    if (t < 48) mbs[t] = mbih0[t];
#pragma unroll
    for (int i = 0; i < 4; i++) {
        int idx = i * 128 + t;           // 512 = 32 samples x 16 gates
        int s = idx >> 4, c = idx & 15;
        float v = gp[((size_t)((c >> 3) * 8192) + n0 + s) * 8 + (c & 7)];
        if (c < 8) gl[s][c] = v; else gr[s][c - 8] = v;
    }
#pragma unroll
    for (int i = 0; i < 8; i++) {
        int idx = i * 128 + t;           // 1024 = 32 x 32
        int s = idx >> 5, c = idx & 31;
        int side = c >> 4, ch = c & 15;
        float a = d_bn[side][0][ch] * d_hpre[side][n0 + s][ch] + d_bn[side][1][ch];
        sh[s][c] = a > 0.f ? a : (__expf(a) - 1.f);
    }
    __syncthreads();
    {
        int e = t >> 4, hh = t & 15;
#pragma unroll 4
        for (int s = 0; s < 32; s++)
            hg[s][t] = fmaf(gl[s][e], sh[s][hh], gr[s][e] * sh[s][16 + hh]);
    }
    __syncthreads();
    {
        int o = t & 15, sg = t >> 4;      // sg 0..7, 4 samples each
        int s0 = sg * 4;
        float a0 = 0.f, a1 = 0.f, a2 = 0.f, a3 = 0.f;
#pragma unroll 4
        for (int k = 0; k < 128; k += 4) {
            float4 wv = *(const float4*)&w2t[o][k];
            float4 g0 = *(const float4*)&hg[s0 + 0][k];
            float4 g1 = *(const float4*)&hg[s0 + 1][k];
            float4 g2 = *(const float4*)&hg[s0 + 2][k];
            float4 g3 = *(const float4*)&hg[s0 + 3][k];
            a0 = fmaf(g0.x, wv.x, a0); a0 = fmaf(g0.y, wv.y, a0);
            a0 = fmaf(g0.z, wv.z, a0); a0 = fmaf(g0.w, wv.w, a0);
            a1 = fmaf(g1.x, wv.x, a1); a1 = fmaf(g1.y, wv.y, a1);
            a1 = fmaf(g1.z, wv.z, a1); a1 = fmaf(g1.w, wv.w, a1);
            a2 = fmaf(g2.x, wv.x, a2); a2 = fmaf(g2.y, wv.y, a2);
            a2 = fmaf(g2.z, wv.z, a2); a2 = fmaf(g2.w, wv.w, a2);
            a3 = fmaf(g3.x, wv.x, a3); a3 = fmaf(g3.y, wv.y, a3);
            a3 = fmaf(g3.z, wv.z, a3); a3 = fmaf(g3.w, wv.w, a3);
        }
        float accs[4] = {a0, a1, a2, a3};
#pragma unroll
        for (int ss = 0; ss < 4; ss++) {
            float bsum = accs[ss];
#pragma unroll
            for (int e = 0; e < 8; e++)
                bsum = fmaf(gl[s0 + ss][e] + gr[s0 + ss][e], b2s[e * 16 + o], bsum);
            zs[s0 + ss][o] = bsum;
        }
    }
    __syncthreads();
    {
        int s = t >> 2, q = t & 3;        // 12 outputs per thread
        float z[16];
#pragma unroll
        for (int h = 0; h < 16; h++) z[h] = zs[s][h];
#pragma unroll
        for (int gi = 0; gi < 12; gi++) {
            int g = q * 12 + gi;
            float acc = mbs[g];
#pragma unroll
            for (int h = 0; h < 16; h++) acc = fmaf(z[h], mWs[g * 16 + h], acc);
            d_xw0[n0 + s][g] = acc;
        }
    }
}

// ---------------- K5: main GRU — R4 layout: lanes 0-15 r&n rows, 16-31 z row ----------------
__global__ void __launch_bounds__(32) mgru_kernel(
    const float* __restrict__ Whh0, const float* __restrict__ bhh0_,
    const float* __restrict__ Wih1, const float* __restrict__ bih1_,
    const float* __restrict__ Whh1, const float* __restrict__ bhh1_)
{
    int b = blockIdx.x;
    int lane = threadIdx.x;
    int j = lane & 15;
    int rowA = (lane < 16) ? lane : 16 + j;
    int rowB = 32 + j;
    float whA[16], whB[16], wiA1[16], wiB1[16], whA1[16], whB1[16];
#pragma unroll
    for (int k = 0; k < 16; k++) {
        whA[k] = Whh0[rowA * 16 + k];  whB[k] = Whh0[rowB * 16 + k];
        wiA1[k] = Wih1[rowA * 16 + k]; wiB1[k] = Wih1[rowB * 16 + k];
        whA1[k] = Whh1[rowA * 16 + k]; whB1[k] = Whh1[rowB * 16 + k];
    }
    float bhA = bhh0_[rowA], bhB = bhh0_[rowB];
    float biA1 = bih1_[rowA], biB1 = bih1_[rowB];
    float bhA1 = bhh1_[rowA], bhB1 = bhh1_[rowB];
    float h0[16], h1[16];
#pragma unroll
    for (int k = 0; k < 16; k++) { h0[k] = 0.f; h1[k] = 0.f; }
    float own0 = 0.f, own1 = 0.f;
    const float* xwp = &d_xw0[b * 128][0];
    float xwA = xwp[rowA], xwB = xwp[rowB];
    for (int t = 0; t < 128; t++) {
        float nxA = 0.f, nxB = 0.f;
        if (t < 127) { nxA = xwp[(t + 1) * 48 + rowA]; nxB = xwp[(t + 1) * 48 + rowB]; }
        // layer 0: lanes<16 hold r locally, lanes>=16 hold z
        float ghA = dot16(whA, h0) + bhA;
        float s = sigt(xwA + ghA);
        float ghB = dot16(whB, h0) + bhB;
        float n = tanha(fmaf(s, ghB, xwB));           // lanes<16
        float z = __shfl_sync(FULL, s, 16 + j);
        float hn = fmaf(z, own0 - n, n);              // lanes<16
        float no0 = own0;
#pragma unroll
        for (int k = 0; k < 16; k++) {
            float v = __shfl_sync(FULL, hn, k);
            h0[k] = v;
            if (k == j) no0 = v;
        }
        own0 = no0;
        // layer 1
        float xwA1 = dot16(wiA1, h0) + biA1;
        float ghA1 = dot16(whA1, h1) + bhA1;
        float s1 = sigt(xwA1 + ghA1);
        float xwB1 = dot16(wiB1, h0) + biB1;
        float ghB1 = dot16(whB1, h1) + bhB1;
        float n1 = tanha(fmaf(s1, ghB1, xwB1));
        float z1 = __shfl_sync(FULL, s1, 16 + j);
        float hn1 = fmaf(z1, own1 - n1, n1);
        float no1 = own1;
#pragma unroll
        for (int k = 0; k < 16; k++) {
            float v = __shfl_sync(FULL, hn1, k);
            h1[k] = v;
            if (k == j) no1 = v;
        }
        own1 = no1;
        xwA = nxA; xwB = nxB;
    }
    if (lane < 16) d_Zlast[b][lane] = h1[lane];
}

// ---------------- K6: decoder expert layer-1 + BN + ELU + gate-weighting ----------------
__global__ void __launch_bounds__(256) dec1_kernel(
    const float* __restrict__ Remote,
    const float* __restrict__ w1, const float* __restrict__ b1,
    const float* __restrict__ gmd, const float* __restrict__ btmd)
{
    __shared__ float w1s[2176];
    __shared__ float sb1[128];
    __shared__ float sh[64][17];
    __shared__ float sa[16], sc[16];
    int tid = threadIdx.x;
    for (int i = tid; i < 2176; i += 256) w1s[i] = w1[i];
    if (tid < 128) sb1[tid] = b1[tid];
    int b = tid >> 2, q = tid & 3;
    float x[17];
#pragma unroll
    for (int k = 0; k < 16; k++) x[k] = d_Zlast[b][k];
    x[16] = Remote[(size_t)b * 16896 + 127 * 132 + 131];
    const float* gp = &d_gate[0][0][0][0];
    float om[8];
#pragma unroll
    for (int e = 0; e < 8; e++) om[e] = gp[(size_t)(8192 + b * 128 + 127) * 8 + e];
    __syncthreads();
    float h[4];
#pragma unroll
    for (int hq = 0; hq < 4; hq++) {
        int hh = q * 4 + hq;
        float acc = 0.f;
#pragma unroll 1
        for (int e = 0; e < 8; e++) {
            float a = sb1[e * 16 + hh];
#pragma unroll
            for (int i = 0; i < 17; i++) a = fmaf(x[i], w1s[e * 272 + i * 16 + hh], a);
            acc = fmaf(om[e], a, acc);
        }
        h[hq] = acc;
        sh[b][hh] = acc;
    }
    __syncthreads();
    if (tid < 16) {
        float s = 0.f, s2 = 0.f;
#pragma unroll 8
        for (int bb = 0; bb < 64; bb++) {
            float v = sh[bb][tid];
            s += v; s2 = fmaf(v, v, s2);
        }
        float m = s * (1.f / 64.f);
        float vv = s2 * (1.f / 64.f) - m * m;
        float a = gmd[tid] * rsqrtf(vv + BNEPS);
        sa[tid] = a;
        sc[tid] = btmd[tid] - m * a;
    }
    __syncthreads();
#pragma unroll
    for (int hq = 0; hq < 4; hq++) {
        int hh = q * 4 + hq;
        float t = sa[hh] * h[hq] + sc[hh];
        float hv = t > 0.f ? t : (__expf(t) - 1.f);
#pragma unroll
        for (int e = 0; e < 8; e++) d_q[b][e * 16 + hh] = om[e] * hv;
    }
}

// ---------------- K7: decoder layer-2 -> output ----------------
__global__ void __launch_bounds__(128) dec2_kernel(
    const float* __restrict__ w2, const float* __restrict__ b2,
    float* __restrict__ out)
{
    int b = blockIdx.x, o = threadIdx.x;
    __shared__ float sq[128];
    sq[o] = d_q[b][o];
    __syncthreads();
    const float* gp = &d_gate[0][0][0][0];
    float acc = 0.f;
#pragma unroll 4
    for (int k = 0; k < 128; k++) acc = fmaf(sq[k], w2[k * 128 + o], acc);
#pragma unroll
    for (int e = 0; e < 8; e++)
        acc = fmaf(gp[(size_t)(8192 + b * 128 + 127) * 8 + e], b2[e * 128 + o], acc);
    out[b * 128 + o] = acc;
}

// ---------------- host ----------------
extern "C" void kernel_launch(void* const* d_in, const int* in_sizes, int n_in,
                              void* d_out, int out_size) {
    const float* Local = (const float*)d_in[0];
    const float* Remote = (const float*)d_in[1];
    const float *gWih0, *gWhh0, *gbih0, *gbhh0, *gWih1, *gWhh1, *gbih1, *gbhh1;
    const float *aew1, *aeb1, *aew2, *aeb2, *aeg, *aebt;
    const float *mdw1, *mdb1, *mdw2, *mdb2, *mdg, *mdbt;
    const float *mWih0, *mWhh0, *mbih0, *mbhh0, *mWih1, *mWhh1, *mbih1, *mbhh1;
#define FP(i) ((const float*)d_in[(i)])
    if (in_sizes[2] == 72) {
        gWih0 = FP(2); gWhh0 = FP(3); gbih0 = FP(4); gbhh0 = FP(5);
        gWih1 = FP(6); gWhh1 = FP(7); gbih1 = FP(8); gbhh1 = FP(9);
        int ae, m;
        if (in_sizes[10] == 16384) { ae = 10; m = 22; }   // signature order
        else                       { m = 10; ae = 18; }   // setup_inputs dict order
        aew1 = FP(ae + 0); aeb1 = FP(ae + 1); aew2 = FP(ae + 2);
        aeb2 = FP(ae + 3); aeg  = FP(ae + 4); aebt = FP(ae + 5);
        mdw1 = FP(ae + 6); mdb1 = FP(ae + 7); mdw2 = FP(ae + 8);
        mdb2 = FP(ae + 9); mdg  = FP(ae + 10); mdbt = FP(ae + 11);
        mWih0 = FP(m + 0); mWhh0 = FP(m + 1); mbih0 = FP(m + 2); mbhh0 = FP(m + 3);
        mWih1 = FP(m + 4); mWhh1 = FP(m + 5); mbih1 = FP(m + 6); mbhh1 = FP(m + 7);
    } else {
        // alphabetical fallback
        aeb1 = FP(2); aeb2 = FP(3); aebt = FP(4); aeg = FP(5); aew1 = FP(6); aew2 = FP(7);
        gWhh0 = FP(8); gWhh1 = FP(9); gWih0 = FP(10); gWih1 = FP(11);
        gbhh0 = FP(12); gbhh1 = FP(13); gbih0 = FP(14); gbih1 = FP(15);
        mWhh0 = FP(16); mWhh1 = FP(17); mWih0 = FP(18); mWih1 = FP(19);
        mbhh0 = FP(20); mbhh1 = FP(21); mbih0 = FP(22); mbih1 = FP(23);
        mdb1 = FP(24); mdb2 = FP(25); mdbt = FP(26); mdg = FP(27); mdw1 = FP(28); mdw2 = FP(29);
    }
#undef FP
    float* out = (float*)d_out;

    mega_kernel<<<528, 128>>>(Local, Remote, gWih0, gWhh0, gbih0, gbhh0,
                              gWih1, gWhh1, gbih1, gbhh1, aew1, aeb1);
    combine_kernel<<<128, 128>>>();
    bnfin_kernel<<<1, 1024>>>(aeg, aebt);
    fuse2_kernel<<<256, 128>>>(aew2, aeb2, mWih0, mbih0);
    mgru_kernel<<<64, 32>>>(mWhh0, mbhh0, mWih1, mbih1, mWhh1, mbhh1);
    dec1_kernel<<<1, 256>>>(Remote, mdw1, mdb1, mdg, mdbt);
    dec2_kernel<<<64, 128>>>(mdw2, mdb2, out);
}

// round 8
// speedup vs baseline: 3.6827x; 1.4872x over previous
#include <cuda_runtime.h>

#define FULL 0xffffffffu
#define BNEPS 1e-5f

// ---------------- scratch (device globals; allocation is forbidden) ----------------
__device__ float d_gate[2][64][128][8];   // softmax gates (side, b, t, e)
__device__ float d_y[2][8192][128];       // ungated expert layer-1 outputs [n][e*16+hh]
__device__ float d_hpre[2][8192][16];     // gated expert layer-1 hidden (pre-BN)
__device__ float d_part[2][256][32];      // per-block BN partials [sum(16) | sumsq(16)]
__device__ float d_bn[2][2][16];          // per-side BN scale/shift
__device__ float d_xw0[8192][48];         // precomputed main-GRU layer0 input projection
__device__ float d_Zlast[64][16];         // main GRU final hidden
__device__ float d_q[64][128];            // decoder gated hidden
__device__ unsigned int d_cnt;            // combine completion counter (self-resetting)

// ---------------- fast math ----------------
__device__ __forceinline__ float tanha(float x) {
    float y;
    asm("tanh.approx.f32 %0, %1;" : "=f"(y) : "f"(x));
    return y;
}
__device__ __forceinline__ float sigt(float x) {          // sigmoid via tanh
    return fmaf(tanha(0.5f * x), 0.5f, 0.5f);
}
typedef unsigned long long ull;
__device__ __forceinline__ ull pack2(float x, float y) {
    ull r;
    asm("mov.b64 %0, {%1, %2};" : "=l"(r) : "f"(x), "f"(y));
    return r;
}
__device__ __forceinline__ void unpack2(ull v, float& x, float& y) {
    asm("mov.b64 {%0, %1}, %2;" : "=f"(x), "=f"(y) : "l"(v));
}
__device__ __forceinline__ ull fma2(ull a, ull b, ull c) {
    ull d;
    asm("fma.rn.f32x2 %0, %1, %2, %3;" : "=l"(d) : "l"(a), "l"(b), "l"(c));
    return d;
}
__device__ __forceinline__ ull add2(ull a, ull b) {
    ull d;
    asm("add.rn.f32x2 %0, %1, %2;" : "=l"(d) : "l"(a), "l"(b));
    return d;
}
// packed dot over 8 floats (4 pairs) with packed bias (bias in lo half)
__device__ __forceinline__ float dot8p(const ull* w, const ull* h, ull bias2) {
    ull a0 = fma2(w[0], h[0], bias2);
    ull a1 = fma2(w[1], h[1], 0ull);
    a0 = fma2(w[2], h[2], a0);
    a1 = fma2(w[3], h[3], a1);
    ull s = add2(a0, a1);
    float lo, hi; unpack2(s, lo, hi);
    return lo + hi;
}
// packed dot over 16 floats (8 pairs) with packed bias
__device__ __forceinline__ float dot16p(const ull* w, const ull* h, ull bias2) {
    ull a0 = fma2(w[0], h[0], bias2);
    ull a1 = fma2(w[1], h[1], 0ull);
    a0 = fma2(w[2], h[2], a0);
    a1 = fma2(w[3], h[3], a1);
    a0 = fma2(w[4], h[4], a0);
    a1 = fma2(w[5], h[5], a1);
    a0 = fma2(w[6], h[6], a0);
    a1 = fma2(w[7], h[7], a1);
    ull s = add2(a0, a1);
    float lo, hi; unpack2(s, lo, hi);
    return lo + hi;
}
__device__ __forceinline__ void loadpack(ull* dst, const float* src, int npairs) {
#pragma unroll
    for (int k = 0; k < 8; k++) {
        if (k < npairs) {
            float2 v = *(const float2*)(src + 2 * k);
            dst[k] = pack2(v.x, v.y);
        }
    }
}

// ---------------- K1 mega: blocks 0-15 = gate GRU; blocks 16-527 = ungated expert GEMM ----------------
__global__ void __launch_bounds__(128) mega_kernel(
    const float* __restrict__ Local, const float* __restrict__ Remote,
    const float* __restrict__ Wih0, const float* __restrict__ Whh0,
    const float* __restrict__ bih0, const float* __restrict__ bhh0,
    const float* __restrict__ Wih1, const float* __restrict__ Whh1,
    const float* __restrict__ bih1, const float* __restrict__ bhh1,
    const float* __restrict__ w1, const float* __restrict__ b1)
{
    __shared__ __align__(16) float2 xs2[4][8][128];

    if (blockIdx.x < 16) {
        // ================= gate GRU (packed math, smem broadcast) =================
        __shared__ __align__(16) float gb[4][2][2][16];  // [warp][layer][buf][2 sides x 8]
        int w = threadIdx.x >> 5;
        int b = blockIdx.x * 4 + w;                       // 0..63
        int lane = threadIdx.x & 31;
        int sub = (lane >> 3) & 1;                        // lanes 16-31 duplicate 0-15
        int j = lane & 7;
        int r1r = 8 + j, r1n = 16 + j;

        float wir[3], wiz[3], win[3];
#pragma unroll
        for (int k = 0; k < 3; k++) {
            wir[k] = Wih0[j * 3 + k];
            wiz[k] = Wih0[r1r * 3 + k];
            win[k] = Wih0[r1n * 3 + k];
        }
        float bir = bih0[j], biz = bih0[r1r], bin = bih0[r1n];
        ull whr2[4], whz2[4], whn2[4], wir12[4], wiz12[4], win12[4],
            whr12[4], whz12[4], whn12[4];
        loadpack(whr2, Whh0 + j * 8, 4);   loadpack(whz2, Whh0 + r1r * 8, 4);
        loadpack(whn2, Whh0 + r1n * 8, 4);
        loadpack(wir12, Wih1 + j * 8, 4);  loadpack(wiz12, Wih1 + r1r * 8, 4);
        loadpack(win12, Wih1 + r1n * 8, 4);
        loadpack(whr12, Whh1 + j * 8, 4);  loadpack(whz12, Whh1 + r1r * 8, 4);
        loadpack(whn12, Whh1 + r1n * 8, 4);
        ull bhr2 = pack2(bhh0[j], 0.f), bhz2 = pack2(bhh0[r1r], 0.f), bhn2 = pack2(bhh0[r1n], 0.f);
        ull bir12 = pack2(bih1[j], 0.f), biz12 = pack2(bih1[r1r], 0.f), bin12 = pack2(bih1[r1n], 0.f);
        ull bhr12 = pack2(bhh1[j], 0.f), bhz12 = pack2(bhh1[r1r], 0.f), bhn12 = pack2(bhh1[r1n], 0.f);

        ull h0p[4], h1p[4];
#pragma unroll
        for (int k = 0; k < 4; k++) { h0p[k] = 0ull; h1p[k] = 0ull; }
        float own0 = 0.f, own1 = 0.f;

        const float* xb = (sub ? Remote : Local) + (size_t)b * 16896 + 128;
        float* outp = &d_gate[sub][b][0][0];
        float4 xc = *(const float4*)xb;

        for (int t = 0; t < 128; t++) {
            float4 xn = xc;
            if (t < 127) xn = *(const float4*)(xb + (size_t)(t + 1) * 132);
            int buf = t & 1;
            // ---- layer 0 ----
            float xwr = fmaf(xc.z, wir[2], fmaf(xc.y, wir[1], fmaf(xc.x, wir[0], bir)));
            float xwz = fmaf(xc.z, wiz[2], fmaf(xc.y, wiz[1], fmaf(xc.x, wiz[0], biz)));
            float xwn = fmaf(xc.z, win[2], fmaf(xc.y, win[1], fmaf(xc.x, win[0], bin)));
            float ghr = dot8p(whr2, h0p, bhr2);
            float ghz = dot8p(whz2, h0p, bhz2);
            float ghn = dot8p(whn2, h0p, bhn2);
            float r = sigt(xwr + ghr);
            float z = sigt(xwz + ghz);
            float n = tanha(fmaf(r, ghn, xwn));
            float hn = fmaf(z, own0 - n, n);
            own0 = hn;
            gb[w][0][buf][sub * 8 + j] = hn;   // lanes 16-31 duplicate same value
            __syncwarp();
            {
                const float* hsrc = &gb[w][0][buf][sub * 8];
                ulonglong2 q0 = *(const ulonglong2*)hsrc;
                ulonglong2 q1 = *(const ulonglong2*)(hsrc + 4);
                h0p[0] = q0.x; h0p[1] = q0.y; h0p[2] = q1.x; h0p[3] = q1.y;
            }
            // ---- layer 1 ----
            float xwr1 = dot8p(wir12, h0p, bir12);
            float xwz1 = dot8p(wiz12, h0p, biz12);
            float xwn1 = dot8p(win12, h0p, bin12);
            float ghr1 = dot8p(whr12, h1p, bhr12);
            float ghz1 = dot8p(whz12, h1p, bhz12);
            float ghn1 = dot8p(whn12, h1p, bhn12);
            float rr1 = sigt(xwr1 + ghr1);
            float zz1 = sigt(xwz1 + ghz1);
            float nn1 = tanha(fmaf(rr1, ghn1, xwn1));
            float hn1 = fmaf(zz1, own1 - nn1, nn1);
            own1 = hn1;
            gb[w][1][buf][sub * 8 + j] = hn1;
            __syncwarp();
            {
                const float* hsrc = &gb[w][1][buf][sub * 8];
                ulonglong2 q0 = *(const ulonglong2*)hsrc;
                ulonglong2 q1 = *(const ulonglong2*)(hsrc + 4);
                h1p[0] = q0.x; h1p[1] = q0.y; h1p[2] = q1.x; h1p[3] = q1.y;
            }
            // ---- softmax over 8 (h1 in (-1,1): no max shift) ----
            float ev = __expf(hn1);
            float ss = ev;
            ss += __shfl_xor_sync(FULL, ss, 1);
            ss += __shfl_xor_sync(FULL, ss, 2);
            ss += __shfl_xor_sync(FULL, ss, 4);
            if (lane < 16) outp[t * 8 + j] = __fdividef(ev, ss);
            xc = xn;
        }
    } else {
        // ================= ungated expert layer-1 GEMM =================
        int bx = blockIdx.x - 16;          // 0..511
        int side = bx >> 8;
        int bq = bx & 255;
        const float* src = side ? Remote : Local;
        int w = threadIdx.x >> 5, lane = threadIdx.x & 31;
        int n0 = bq * 32 + w * 8;

#pragma unroll
        for (int s = 0; s < 8; s++) {
            int n = n0 + s;
            int bb = n >> 7, t = n & 127;
            float4 v = *(const float4*)(src + (size_t)bb * 16896 + t * 132 + lane * 4);
            xs2[w][s][lane * 4 + 0] = make_float2(v.x, v.x);
            xs2[w][s][lane * 4 + 1] = make_float2(v.y, v.y);
            xs2[w][s][lane * 4 + 2] = make_float2(v.z, v.z);
            xs2[w][s][lane * 4 + 3] = make_float2(v.w, v.w);
        }
        int e = lane >> 2, hq = lane & 3;
        __syncthreads();

        ull a01[8], a23[8];
#pragma unroll
        for (int s = 0; s < 8; s++) { a01[s] = 0ull; a23[s] = 0ull; }

        const float* wbase = w1 + (size_t)e * 2048 + hq * 4;   // (e*128+i)*16 + 4*hq
#pragma unroll 4
        for (int i = 0; i < 128; i++) {
            float4 wv = *(const float4*)(wbase + i * 16);
            ull w01 = pack2(wv.x, wv.y);
            ull w23 = pack2(wv.z, wv.w);
#pragma unroll
            for (int s = 0; s < 8; s++) {
                ull xp = *(const ull*)&xs2[w][s][i];
                a01[s] = fma2(w01, xp, a01[s]);
                a23[s] = fma2(w23, xp, a23[s]);
            }
        }
        float4 bq4 = *(const float4*)(b1 + e * 16 + hq * 4);
#pragma unroll
        for (int s = 0; s < 8; s++) {
            float v0, v1, v2, v3;
            unpack2(a01[s], v0, v1);
            unpack2(a23[s], v2, v3);
            *(float4*)&d_y[side][n0 + s][lane * 4] =
                make_float4(v0 + bq4.x, v1 + bq4.y, v2 + bq4.z, v3 + bq4.w);
        }
    }
}

// ---------------- K2: gates -> hpre + BN partials; last block finalizes BN ----------------
// 512 blocks x 128 threads; 32 samples per block
__global__ void __launch_bounds__(128) combine_kernel(
    const float* __restrict__ ae_g, const float* __restrict__ ae_bt)
{
    __shared__ __align__(16) float ys[32][128];
    __shared__ float gs[32][8];
    __shared__ float hsm[32][16];
    __shared__ float sred[128];
    __shared__ float stot[2][32];
    __shared__ int lastflag;
    int t = threadIdx.x;
    int blk = blockIdx.x;                 // 0..511
    int side = blk >> 8;
    int grp = blk & 255;
    int n0 = grp * 32;
    const float* gp = &d_gate[0][0][0][0];

#pragma unroll
    for (int i = 0; i < 8; i++) {
        int idx = i * 128 + t;            // 1024 float4
        int s = idx >> 5, c = idx & 31;
        ((float4*)&ys[s][0])[c] = ((const float4*)&d_y[side][n0 + s][0])[c];
    }
#pragma unroll
    for (int i = 0; i < 2; i++) {
        int idx = i * 128 + t;            // 256 gates
        int s = idx >> 3, e = idx & 7;
        gs[s][e] = gp[((size_t)side * 8192 + n0 + s) * 8 + e];
    }
    __syncthreads();
    {
        int s = t >> 2, q = t & 3;
        float4 acc = {0.f, 0.f, 0.f, 0.f};
#pragma unroll
        for (int e = 0; e < 8; e++) {
            float g = gs[s][e];
            float4 y4 = *(const float4*)&ys[s][e * 16 + q * 4];
            acc.x = fmaf(g, y4.x, acc.x); acc.y = fmaf(g, y4.y, acc.y);
            acc.z = fmaf(g, y4.z, acc.z); acc.w = fmaf(g, y4.w, acc.w);
        }
        *(float4*)&d_hpre[side][n0 + s][q * 4] = acc;
        *(float4*)&hsm[s][q * 4] = acc;
    }
    __syncthreads();
    if (t < 32) {
        int c = t & 15, kind = t >> 4;
        float a = 0.f;
#pragma unroll 8
        for (int ss = 0; ss < 32; ss++) {
            float v = hsm[ss][c];
            a += kind ? v * v : v;
        }
        d_part[side][grp][t] = a;
    }
    // ---- last-block BN finalize ----
    __threadfence();
    __syncthreads();
    if (t == 0) {
        unsigned int v = atomicAdd(&d_cnt, 1u);
        lastflag = (v == 511u);
    }
    __syncthreads();
    if (lastflag) {
        int sd = t >> 6, rem = t & 63;
        int c = rem & 31, half = rem >> 5;
        float a = 0.f;
#pragma unroll 8
        for (int k = 0; k < 128; k++) a += d_part[sd][half * 128 + k][c];
        sred[t] = a;
        __syncthreads();
        if (t < 64) {
            int s2 = t >> 5, c2 = t & 31;
            stot[s2][c2] = sred[s2 * 64 + c2] + sred[s2 * 64 + 32 + c2];
        }
        __syncthreads();
        if (t < 32) {
            int s2 = t >> 4, ch = t & 15;
            float m = stot[s2][ch] * (1.f / 8192.f);
            float vv = stot[s2][16 + ch] * (1.f / 8192.f) - m * m;
            float a2 = ae_g[ch] * rsqrtf(vv + BNEPS);
            d_bn[s2][0][ch] = a2;
            d_bn[s2][1][ch] = ae_bt[ch] - m * a2;
        }
        if (t == 0) d_cnt = 0u;          // reset for next graph replay
    }
}

// ---------------- K3: fused BN+ELU + gated-combine GEMM + projection ----------------
__global__ void __launch_bounds__(128) fuse2_kernel(
    const float* __restrict__ w2, const float* __restrict__ b2,
    const float* __restrict__ mWih0, const float* __restrict__ mbih0)
{
    __shared__ float sh[32][33];          // ELU'd hidden: [s][0..15]=L, [16..31]=R
    __shared__ __align__(16) float hg[32][132];
    __shared__ __align__(16) float w2t[16][132];   // transposed w2: [o][k]
    __shared__ float b2s[128];
    __shared__ float gl[32][8], gr[32][8];
    __shared__ float zs[32][17];
    __shared__ __align__(16) float mWs[768];
    __shared__ float mbs[48];
    int t = threadIdx.x;
    int n0 = blockIdx.x * 32;
    const float* gp = &d_gate[0][0][0][0];

#pragma unroll
    for (int i = 0; i < 16; i++) {
        int idx = i * 128 + t;           // 2048
        int o = idx >> 7, k = idx & 127;
        w2t[o][k] = w2[k * 16 + o];
    }
    b2s[t] = b2[t];
#pragma unroll
    for (int i = 0; i < 6; i++) mWs[i * 128 + t] = mWih0[i * 128 + t];
    if (t < 48) mbs[t] = mbih0[t];
#pragma unroll
    for (int i = 0; i < 4; i++) {
        int idx = i * 128 + t;           // 512 = 32 samples x 16 gates
        int s = idx >> 4, c = idx & 15;
        float v = gp[((size_t)((c >> 3) * 8192) + n0 + s) * 8 + (c & 7)];
        if (c < 8) gl[s][c] = v; else gr[s][c - 8] = v;
    }
#pragma unroll
    for (int i = 0; i < 8; i++) {
        int idx = i * 128 + t;           // 1024 = 32 x 32
        int s = idx >> 5, c = idx & 31;
        int side = c >> 4, ch = c & 15;
        float a = d_bn[side][0][ch] * d_hpre[side][n0 + s][ch] + d_bn[side][1][ch];
        sh[s][c] = a > 0.f ? a : (__expf(a) - 1.f);
    }
    __syncthreads();
    {
        int e = t >> 4, hh = t & 15;
#pragma unroll 4
        for (int s = 0; s < 32; s++)
            hg[s][t] = fmaf(gl[s][e], sh[s][hh], gr[s][e] * sh[s][16 + hh]);
    }
    __syncthreads();
    {
        int o = t & 15, sg = t >> 4;      // sg 0..7, 4 samples each
        int s0 = sg * 4;
        float a0 = 0.f, a1 = 0.f, a2 = 0.f, a3 = 0.f;
#pragma unroll 4
        for (int k = 0; k < 128; k += 4) {
            float4 wv = *(const float4*)&w2t[o][k];
            float4 g0 = *(const float4*)&hg[s0 + 0][k];
            float4 g1 = *(const float4*)&hg[s0 + 1][k];
            float4 g2 = *(const float4*)&hg[s0 + 2][k];
            float4 g3 = *(const float4*)&hg[s0 + 3][k];
            a0 = fmaf(g0.x, wv.x, a0); a0 = fmaf(g0.y, wv.y, a0);
            a0 = fmaf(g0.z, wv.z, a0); a0 = fmaf(g0.w, wv.w, a0);
            a1 = fmaf(g1.x, wv.x, a1); a1 = fmaf(g1.y, wv.y, a1);
            a1 = fmaf(g1.z, wv.z, a1); a1 = fmaf(g1.w, wv.w, a1);
            a2 = fmaf(g2.x, wv.x, a2); a2 = fmaf(g2.y, wv.y, a2);
            a2 = fmaf(g2.z, wv.z, a2); a2 = fmaf(g2.w, wv.w, a2);
            a3 = fmaf(g3.x, wv.x, a3); a3 = fmaf(g3.y, wv.y, a3);
            a3 = fmaf(g3.z, wv.z, a3); a3 = fmaf(g3.w, wv.w, a3);
        }
        float accs[4] = {a0, a1, a2, a3};
#pragma unroll
        for (int ss = 0; ss < 4; ss++) {
            float bsum = accs[ss];
#pragma unroll
            for (int e = 0; e < 8; e++)
                bsum = fmaf(gl[s0 + ss][e] + gr[s0 + ss][e], b2s[e * 16 + o], bsum);
            zs[s0 + ss][o] = bsum;
        }
    }
    __syncthreads();
    {
        int s = t >> 2, q = t & 3;        // 12 outputs per thread
        float z[16];
#pragma unroll
        for (int h = 0; h < 16; h++) z[h] = zs[s][h];
#pragma unroll
        for (int gi = 0; gi < 12; gi++) {
            int g = q * 12 + gi;
            float acc = mbs[g];
#pragma unroll
            for (int h = 0; h < 16; h++) acc = fmaf(z[h], mWs[g * 16 + h], acc);
            d_xw0[n0 + s][g] = acc;
        }
    }
}

// ---------------- K4: main GRU — packed math, smem broadcast ----------------
// 1 warp per sample; lanes 0-15: r+n rows, lanes 16-31: z row
__global__ void __launch_bounds__(32) mgru_kernel(
    const float* __restrict__ Whh0, const float* __restrict__ bhh0_,
    const float* __restrict__ Wih1, const float* __restrict__ bih1_,
    const float* __restrict__ Whh1, const float* __restrict__ bhh1_)
{
    __shared__ __align__(16) float hs[2][2][16];    // [layer][buf][16]
    int b = blockIdx.x;
    int lane = threadIdx.x;
    int j = lane & 15;
    int rowA = (lane < 16) ? j : 16 + j;   // r (lanes<16) or z (lanes>=16)
    int rowB = 32 + j;                     // n row (lanes<16)

    ull whA2[8], whB2[8], wiA12[8], wiB12[8], whA12[8], whB12[8];
    loadpack(whA2, Whh0 + rowA * 16, 8);
    loadpack(whB2, Whh0 + rowB * 16, 8);
    loadpack(wiA12, Wih1 + rowA * 16, 8);
    loadpack(wiB12, Wih1 + rowB * 16, 8);
    loadpack(whA12, Whh1 + rowA * 16, 8);
    loadpack(whB12, Whh1 + rowB * 16, 8);
    ull bhA2 = pack2(bhh0_[rowA], 0.f), bhB2 = pack2(bhh0_[rowB], 0.f);
    ull biA2 = pack2(bih1_[rowA], 0.f), biB2 = pack2(bih1_[rowB], 0.f);
    ull bhA12 = pack2(bhh1_[rowA], 0.f), bhB12 = pack2(bhh1_[rowB], 0.f);

    ull h0p[8], h1p[8];
#pragma unroll
    for (int k = 0; k < 8; k++) { h0p[k] = 0ull; h1p[k] = 0ull; }
    float own0 = 0.f, own1 = 0.f;

    const float* xwp = &d_xw0[b * 128][0];
    float xwA = xwp[rowA], xwB = xwp[rowB];

    for (int t = 0; t < 128; t++) {
        float nxA = 0.f, nxB = 0.f;
        if (t < 127) { nxA = xwp[(t + 1) * 48 + rowA]; nxB = xwp[(t + 1) * 48 + rowB]; }
        int buf = t & 1;
        // ---- layer 0 ----
        float ghA = dot16p(whA2, h0p, bhA2);
        float s = sigt(xwA + ghA);                      // r (lanes<16) / z (lanes>=16)
        float ghB = dot16p(whB2, h0p, bhB2);
        float n = tanha(fmaf(s, ghB, xwB));             // lanes<16
        float z = __shfl_sync(FULL, s, 16 + j);
        float hn = fmaf(z, own0 - n, n);                // lanes<16
        own0 = hn;
        if (lane < 16) hs[0][buf][j] = hn;
        __syncwarp();
        {
            const float* hsrc = &hs[0][buf][0];
            ulonglong2 q0 = *(const ulonglong2*)hsrc;
            ulonglong2 q1 = *(const ulonglong2*)(hsrc + 4);
            ulonglong2 q2 = *(const ulonglong2*)(hsrc + 8);
            ulonglong2 q3 = *(const ulonglong2*)(hsrc + 12);
            h0p[0] = q0.x; h0p[1] = q0.y; h0p[2] = q1.x; h0p[3] = q1.y;
            h0p[4] = q2.x; h0p[5] = q2.y; h0p[6] = q3.x; h0p[7] = q3.y;
        }
        // ---- layer 1 ----
        float xwA1 = dot16p(wiA12, h0p, biA2);
        float ghA1 = dot16p(whA12, h1p, bhA12);
        float s1 = sigt(xwA1 + ghA1);
        float xwB1 = dot16p(wiB12, h0p, biB2);
        float ghB1 = dot16p(whB12, h1p, bhB12);
        float n1 = tanha(fmaf(s1, ghB1, xwB1));
        float z1 = __shfl_sync(FULL, s1, 16 + j);
        float hn1 = fmaf(z1, own1 - n1, n1);
        own1 = hn1;
        if (lane < 16) hs[1][buf][j] = hn1;
        __syncwarp();
        {
            const float* hsrc = &hs[1][buf][0];
            ulonglong2 q0 = *(const ulonglong2*)hsrc;
            ulonglong2 q1 = *(const ulonglong2*)(hsrc + 4);
            ulonglong2 q2 = *(const ulonglong2*)(hsrc + 8);
            ulonglong2 q3 = *(const ulonglong2*)(hsrc + 12);
            h1p[0] = q0.x; h1p[1] = q0.y; h1p[2] = q1.x; h1p[3] = q1.y;
            h1p[4] = q2.x; h1p[5] = q2.y; h1p[6] = q3.x; h1p[7] = q3.y;
        }
        xwA = nxA; xwB = nxB;
    }
    if (lane < 16) d_Zlast[b][j] = own1;
}

// ---------------- K5: decoder expert layer-1 + BN + ELU + gate-weighting ----------------
__global__ void __launch_bounds__(256) dec1_kernel(
    const float* __restrict__ Remote,
    const float* __restrict__ w1, const float* __restrict__ b1,
    const float* __restrict__ gmd, const float* __restrict__ btmd)
{
    __shared__ float w1s[2176];
    __shared__ float sb1[128];
    __shared__ float sh[64][17];
    __shared__ float sa[16], sc[16];
    int tid = threadIdx.x;
    for (int i = tid; i < 2176; i += 256) w1s[i] = w1[i];
    if (tid < 128) sb1[tid] = b1[tid];
    int b = tid >> 2, q = tid & 3;
    float x[17];
#pragma unroll
    for (int k = 0; k < 16; k++) x[k] = d_Zlast[b][k];
    x[16] = Remote[(size_t)b * 16896 + 127 * 132 + 131];
    const float* gp = &d_gate[0][0][0][0];
    float om[8];
#pragma unroll
    for (int e = 0; e < 8; e++) om[e] = gp[(size_t)(8192 + b * 128 + 127) * 8 + e];
    __syncthreads();
    float h[4];
#pragma unroll
    for (int hq = 0; hq < 4; hq++) {
        int hh = q * 4 + hq;
        float acc = 0.f;
#pragma unroll 1
        for (int e = 0; e < 8; e++) {
            float a = sb1[e * 16 + hh];
#pragma unroll
            for (int i = 0; i < 17; i++) a = fmaf(x[i], w1s[e * 272 + i * 16 + hh], a);
            acc = fmaf(om[e], a, acc);
        }
        h[hq] = acc;
        sh[b][hh] = acc;
    }
    __syncthreads();
    if (tid < 16) {
        float s = 0.f, s2 = 0.f;
#pragma unroll 8
        for (int bb = 0; bb < 64; bb++) {
            float v = sh[bb][tid];
            s += v; s2 = fmaf(v, v, s2);
        }
        float m = s * (1.f / 64.f);
        float vv = s2 * (1.f / 64.f) - m * m;
        float a = gmd[tid] * rsqrtf(vv + BNEPS);
        sa[tid] = a;
        sc[tid] = btmd[tid] - m * a;
    }
    __syncthreads();
#pragma unroll
    for (int hq = 0; hq < 4; hq++) {
        int hh = q * 4 + hq;
        float t = sa[hh] * h[hq] + sc[hh];
        float hv = t > 0.f ? t : (__expf(t) - 1.f);
#pragma unroll
        for (int e = 0; e < 8; e++) d_q[b][e * 16 + hh] = om[e] * hv;
    }
}

// ---------------- K6: decoder layer-2 -> output ----------------
__global__ void __launch_bounds__(128) dec2_kernel(
    const float* __restrict__ w2, const float* __restrict__ b2,
    float* __restrict__ out)
{
    int b = blockIdx.x, o = threadIdx.x;
    __shared__ float sq[128];
    sq[o] = d_q[b][o];
    __syncthreads();
    const float* gp = &d_gate[0][0][0][0];
    float acc = 0.f;
#pragma unroll 4
    for (int k = 0; k < 128; k++) acc = fmaf(sq[k], w2[k * 128 + o], acc);
#pragma unroll
    for (int e = 0; e < 8; e++)
        acc = fmaf(gp[(size_t)(8192 + b * 128 + 127) * 8 + e], b2[e * 128 + o], acc);
    out[b * 128 + o] = acc;
}

// ---------------- host ----------------
extern "C" void kernel_launch(void* const* d_in, const int* in_sizes, int n_in,
                              void* d_out, int out_size) {
    const float* Local = (const float*)d_in[0];
    const float* Remote = (const float*)d_in[1];
    const float *gWih0, *gWhh0, *gbih0, *gbhh0, *gWih1, *gWhh1, *gbih1, *gbhh1;
    const float *aew1, *aeb1, *aew2, *aeb2, *aeg, *aebt;
    const float *mdw1, *mdb1, *mdw2, *mdb2, *mdg, *mdbt;
    const float *mWih0, *mWhh0, *mbih0, *mbhh0, *mWih1, *mWhh1, *mbih1, *mbhh1;
#define FP(i) ((const float*)d_in[(i)])
    if (in_sizes[2] == 72) {
        gWih0 = FP(2); gWhh0 = FP(3); gbih0 = FP(4); gbhh0 = FP(5);
        gWih1 = FP(6); gWhh1 = FP(7); gbih1 = FP(8); gbhh1 = FP(9);
        int ae, m;
        if (in_sizes[10] == 16384) { ae = 10; m = 22; }   // signature order
        else                       { m = 10; ae = 18; }   // setup_inputs dict order
        aew1 = FP(ae + 0); aeb1 = FP(ae + 1); aew2 = FP(ae + 2);
        aeb2 = FP(ae + 3); aeg  = FP(ae + 4); aebt = FP(ae + 5);
        mdw1 = FP(ae + 6); mdb1 = FP(ae + 7); mdw2 = FP(ae + 8);
        mdb2 = FP(ae + 9); mdg  = FP(ae + 10); mdbt = FP(ae + 11);
        mWih0 = FP(m + 0); mWhh0 = FP(m + 1); mbih0 = FP(m + 2); mbhh0 = FP(m + 3);
        mWih1 = FP(m + 4); mWhh1 = FP(m + 5); mbih1 = FP(m + 6); mbhh1 = FP(m + 7);
    } else {
        // alphabetical fallback
        aeb1 = FP(2); aeb2 = FP(3); aebt = FP(4); aeg = FP(5); aew1 = FP(6); aew2 = FP(7);
        gWhh0 = FP(8); gWhh1 = FP(9); gWih0 = FP(10); gWih1 = FP(11);
        gbhh0 = FP(12); gbhh1 = FP(13); gbih0 = FP(14); gbih1 = FP(15);
        mWhh0 = FP(16); mWhh1 = FP(17); mWih0 = FP(18); mWih1 = FP(19);
        mbhh0 = FP(20); mbhh1 = FP(21); mbih0 = FP(22); mbih1 = FP(23);
        mdb1 = FP(24); mdb2 = FP(25); mdbt = FP(26); mdg = FP(27); mdw1 = FP(28); mdw2 = FP(29);
    }
#undef FP
    float* out = (float*)d_out;

    mega_kernel<<<528, 128>>>(Local, Remote, gWih0, gWhh0, gbih0, gbhh0,
                              gWih1, gWhh1, gbih1, gbhh1, aew1, aeb1);
    combine_kernel<<<512, 128>>>(aeg, aebt);
    fuse2_kernel<<<256, 128>>>(aew2, aeb2, mWih0, mbih0);
    mgru_kernel<<<64, 32>>>(mWhh0, mbhh0, mWih1, mbih1, mWhh1, mbhh1);
    dec1_kernel<<<1, 256>>>(Remote, mdw1, mdb1, mdg, mdbt);
    dec2_kernel<<<64, 128>>>(mdw2, mdb2, out);
}